// round 8
// baseline (speedup 1.0000x reference)
#include <cuda_runtime.h>
#include <cuda_bf16.h>

#define BB 8
#define NN 1024
#define HIDD 1024
#define HH 16
#define DD 64
#define M_TOT (BB * NN)   // 8192

// ---------------------------------------------------------------------------
// Scratch (static __device__ arrays — allocation-free per harness rules)
// ---------------------------------------------------------------------------
__device__ __nv_bfloat16 g_axh[3ll * M_TOT * HIDD];   // x hi  (q,k,v inputs)
__device__ __nv_bfloat16 g_axl[3ll * M_TOT * HIDD];   // x lo
__device__ __nv_bfloat16 g_bwh[4ll * HIDD * HIDD];    // W^T hi (q,k,v,o) [N,K]
__device__ __nv_bfloat16 g_bwl[4ll * HIDD * HIDD];    // W^T lo
__device__ __nv_bfloat16 g_qh[(size_t)BB * HH * NN * DD];  // [B,H,N,D] pre-scaled
__device__ __nv_bfloat16 g_ql[(size_t)BB * HH * NN * DD];
__device__ __nv_bfloat16 g_kh[(size_t)BB * HH * NN * DD];
__device__ __nv_bfloat16 g_kl[(size_t)BB * HH * NN * DD];
__device__ __nv_bfloat16 g_vth[(size_t)BB * HH * DD * NN]; // [B,H,D,N] transposed
__device__ __nv_bfloat16 g_vtl[(size_t)BB * HH * DD * NN];
__device__ __nv_bfloat16 g_cxh[(size_t)M_TOT * HIDD]; // ctx hi [B*N, H*D]
__device__ __nv_bfloat16 g_cxl[(size_t)M_TOT * HIDD]; // ctx lo

// ---------------------------------------------------------------------------
// PTX helpers (plain sm_80-era PTX — compiles at compute_103)
// ---------------------------------------------------------------------------
__device__ __forceinline__ unsigned smem_u32(const void* p) {
    unsigned a;
    asm("{ .reg .u64 t; cvta.to.shared.u64 t, %1; cvt.u32.u64 %0, t; }"
        : "=r"(a) : "l"(p));
    return a;
}
#define CP_ASYNC16(dst, src) \
    asm volatile("cp.async.cg.shared.global [%0], [%1], 16;" \
                 :: "r"(dst), "l"(src) : "memory")
#define CP_COMMIT() asm volatile("cp.async.commit_group;" ::: "memory")
#define CP_WAIT(n)  asm volatile("cp.async.wait_group %0;" :: "n"(n) : "memory")

#define LDMATRIX_X4(r0, r1, r2, r3, addr) \
    asm volatile("ldmatrix.sync.aligned.m8n8.x4.shared.b16 {%0,%1,%2,%3}, [%4];" \
                 : "=r"(r0), "=r"(r1), "=r"(r2), "=r"(r3) : "r"(addr))

#define MMA_BF16(c, a, b0, b1) \
    asm volatile("mma.sync.aligned.m16n8k16.row.col.f32.bf16.bf16.f32 " \
                 "{%0,%1,%2,%3}, {%4,%5,%6,%7}, {%8,%9}, {%0,%1,%2,%3};" \
                 : "+f"((c)[0]), "+f"((c)[1]), "+f"((c)[2]), "+f"((c)[3]) \
                 : "r"((a)[0]), "r"((a)[1]), "r"((a)[2]), "r"((a)[3]), \
                   "r"(b0), "r"(b1))

#define SWZ(x) ((x) ^ (((x) >> 3) & 0x70))

__device__ __forceinline__ unsigned pack_bf16(float x, float y) {
    __nv_bfloat162 t;
    t.x = __float2bfloat16(x);
    t.y = __float2bfloat16(y);
    return *(unsigned*)&t;
}
__device__ __forceinline__ void split2(float x, float y, unsigned& h, unsigned& l) {
    __nv_bfloat16 hx = __float2bfloat16(x), hy = __float2bfloat16(y);
    __nv_bfloat162 hh; hh.x = hx; hh.y = hy;
    h = *(unsigned*)&hh;
    l = pack_bf16(x - __bfloat162float(hx), y - __bfloat162float(hy));
}

// ---------------------------------------------------------------------------
// conv_x: fp32 [8192,1024] -> bf16 hi/lo. grid (8192, 3), 256 thr.
// ---------------------------------------------------------------------------
__global__ __launch_bounds__(256) void conv_x_kernel(
    const float* __restrict__ xq, const float* __restrict__ xk,
    const float* __restrict__ xv)
{
    const int z = blockIdx.y;
    const float* X = (z == 0) ? xq : (z == 1) ? xk : xv;
    __nv_bfloat16* Ah = g_axh + (size_t)z * M_TOT * HIDD;
    __nv_bfloat16* Al = g_axl + (size_t)z * M_TOT * HIDD;

    const size_t i = (size_t)blockIdx.x * 256 + threadIdx.x;  // float4 idx
    float4 v = ((const float4*)X)[i];

    __nv_bfloat16 h0 = __float2bfloat16(v.x), h1 = __float2bfloat16(v.y);
    __nv_bfloat16 h2 = __float2bfloat16(v.z), h3 = __float2bfloat16(v.w);
    float l0 = v.x - __bfloat162float(h0), l1 = v.y - __bfloat162float(h1);
    float l2 = v.z - __bfloat162float(h2), l3 = v.w - __bfloat162float(h3);

    __nv_bfloat162* Ah2 = (__nv_bfloat162*)Ah;
    __nv_bfloat162* Al2 = (__nv_bfloat162*)Al;
    Ah2[2 * i + 0] = __nv_bfloat162(h0, h1);
    Ah2[2 * i + 1] = __nv_bfloat162(h2, h3);
    Al2[2 * i + 0] = __nv_bfloat162(__float2bfloat16(l0), __float2bfloat16(l1));
    Al2[2 * i + 1] = __nv_bfloat162(__float2bfloat16(l2), __float2bfloat16(l3));
}

// ---------------------------------------------------------------------------
// conv_w: W [K,N] fp32 -> W^T [N,K] bf16 hi/lo. grid (32,32,4), block (32,8).
// ---------------------------------------------------------------------------
__global__ void conv_w_kernel(
    const float* __restrict__ Wq, const float* __restrict__ Wk,
    const float* __restrict__ Wv, const float* __restrict__ Wo)
{
    __shared__ float t[32][33];
    const int z = blockIdx.z;
    const float* W = (z == 0) ? Wq : (z == 1) ? Wk : (z == 2) ? Wv : Wo;
    __nv_bfloat16* Bh = g_bwh + (size_t)z * HIDD * HIDD;
    __nv_bfloat16* Bl = g_bwl + (size_t)z * HIDD * HIDD;

    const int tx = threadIdx.x, ty = threadIdx.y;
    const int k0 = blockIdx.x * 32, n0 = blockIdx.y * 32;

#pragma unroll
    for (int i = 0; i < 4; i++)
        t[ty + 8 * i][tx] = W[(size_t)(k0 + ty + 8 * i) * HIDD + n0 + tx];
    __syncthreads();
#pragma unroll
    for (int i = 0; i < 4; i++) {
        const int n = n0 + ty + 8 * i;
        const int k = k0 + tx;
        const float v = t[tx][ty + 8 * i];
        __nv_bfloat16 h = __float2bfloat16(v);
        Bh[(size_t)n * HIDD + k] = h;
        Bl[(size_t)n * HIDD + k] = __float2bfloat16(v - __bfloat162float(h));
    }
}

// ---------------------------------------------------------------------------
// mma.sync bf16 split GEMM, fused-term edition.
// CTA tile M=128 x N=128. Per stage one BK=32 k-block with hi|lo packed in a
// 128B row (cols 0-31 hi, 32-63 lo). 32 stages (32*32 = K=1024), 3 MMA terms
// per stage (AhBh + AlBh + AhBl) with fragment reuse. Double-buffered cp.async.
// ---------------------------------------------------------------------------
#define GEMM_SMEM (2 * 32768)
#define GEMM_STAGES 32

__global__ __launch_bounds__(256, 2) void gemm_kernel(
    const float* __restrict__ bq, const float* __restrict__ bk,
    const float* __restrict__ bv, float* out_param, int is_qkv)
{
    extern __shared__ char smem[];
    const unsigned sb = smem_u32(smem);
    const unsigned uA0 = sb, uB0 = sb + 16384;
    const unsigned uA1 = sb + 32768, uB1 = sb + 49152;

    const int tid = threadIdx.x;
    const int wid = tid >> 5, lane = tid & 31;
    const int wm = wid >> 1, wn = wid & 1;          // warp 4x2
    const int m0 = blockIdx.y * 128;
    const int n0 = blockIdx.x * 128;
    const int z = blockIdx.z;

    const __nv_bfloat16 *Ah, *Al, *Bh, *Bl;
    const float* bias;
    float scale;
    if (is_qkv) {
        Ah = g_axh + (size_t)z * M_TOT * HIDD;
        Al = g_axl + (size_t)z * M_TOT * HIDD;
        Bh = g_bwh + (size_t)z * HIDD * HIDD;
        Bl = g_bwl + (size_t)z * HIDD * HIDD;
        bias = (z == 0) ? bq : (z == 1) ? bk : bv;
        scale = (z == 0) ? 0.125f : 1.0f;
    } else {
        Ah = g_cxh; Al = g_cxl;
        Bh = g_bwh + 3ll * HIDD * HIDD;
        Bl = g_bwl + 3ll * HIDD * HIDD;
        bias = bq;            // bo passed in slot 0
        scale = 1.0f;
    }

    float c[16][4];
#pragma unroll
    for (int i = 0; i < 16; i++)
#pragma unroll
        for (int j = 0; j < 4; j++) c[i][j] = 0.0f;

    // one stage = one BK=32 k-block: A row = [hi 64B | lo 64B], same for B
    auto load_stage = [&](int kb, unsigned ua, unsigned ub) {
        const int kk0 = kb * 32;
#pragma unroll
        for (int t = 0; t < 4; t++) {
            const int ch = tid + t * 256;      // 0..1023
            const int row = ch >> 3;
            const int half = (ch >> 2) & 1;    // 0=hi, 1=lo
            const int c4 = ch & 3;             // 16B chunk within 64B
            const unsigned off = SWZ(row * 128 + half * 64 + c4 * 16);
            const __nv_bfloat16* sa =
                (half ? Al : Ah) + (size_t)(m0 + row) * HIDD + kk0 + c4 * 8;
            CP_ASYNC16(ua + off, sa);
            const __nv_bfloat16* sbp =
                (half ? Bl : Bh) + (size_t)(n0 + row) * HIDD + kk0 + c4 * 8;
            CP_ASYNC16(ub + off, sbp);
        }
        CP_COMMIT();
    };

    load_stage(0, uA0, uB0);

    const int a_r = wm * 32 + (lane & 15);
    const int a_c16 = (lane >> 4);
    const int b_r = wn * 64 + ((lane >> 4) & 1) * 8 + (lane & 7);
    const int b_c16 = (lane >> 3) & 1;

    for (int s = 0; s < GEMM_STAGES; s++) {
        const unsigned ua = (s & 1) ? uA1 : uA0;
        const unsigned ub = (s & 1) ? uB1 : uB0;
        if (s + 1 < GEMM_STAGES) {
            load_stage(s + 1, (s & 1) ? uA0 : uA1, (s & 1) ? uB0 : uB1);
            CP_WAIT(1);
        } else {
            CP_WAIT(0);
        }
        __syncthreads();

#pragma unroll
        for (int ks = 0; ks < 2; ks++) {
            unsigned ah[2][4];
#pragma unroll
            for (int mi = 0; mi < 2; mi++)
                LDMATRIX_X4(ah[mi][0], ah[mi][1], ah[mi][2], ah[mi][3],
                            ua + SWZ((a_r + mi * 16) * 128 + ks * 32 + a_c16 * 16));
            unsigned bh[4][4];
#pragma unroll
            for (int p = 0; p < 4; p++)
                LDMATRIX_X4(bh[p][0], bh[p][1], bh[p][2], bh[p][3],
                            ub + SWZ((b_r + p * 16) * 128 + ks * 32 + b_c16 * 16));
            // Ah*Bh
#pragma unroll
            for (int mi = 0; mi < 2; mi++)
#pragma unroll
                for (int p = 0; p < 4; p++) {
                    MMA_BF16(c[mi * 8 + p * 2 + 0], ah[mi], bh[p][0], bh[p][1]);
                    MMA_BF16(c[mi * 8 + p * 2 + 1], ah[mi], bh[p][2], bh[p][3]);
                }
            // Al*Bh (reuse bh)
            unsigned al_[2][4];
#pragma unroll
            for (int mi = 0; mi < 2; mi++)
                LDMATRIX_X4(al_[mi][0], al_[mi][1], al_[mi][2], al_[mi][3],
                            ua + SWZ((a_r + mi * 16) * 128 + 64 + ks * 32 + a_c16 * 16));
#pragma unroll
            for (int mi = 0; mi < 2; mi++)
#pragma unroll
                for (int p = 0; p < 4; p++) {
                    MMA_BF16(c[mi * 8 + p * 2 + 0], al_[mi], bh[p][0], bh[p][1]);
                    MMA_BF16(c[mi * 8 + p * 2 + 1], al_[mi], bh[p][2], bh[p][3]);
                }
            // Ah*Bl (reuse ah)
            unsigned bl_[4][4];
#pragma unroll
            for (int p = 0; p < 4; p++)
                LDMATRIX_X4(bl_[p][0], bl_[p][1], bl_[p][2], bl_[p][3],
                            ub + SWZ((b_r + p * 16) * 128 + 64 + ks * 32 + b_c16 * 16));
#pragma unroll
            for (int mi = 0; mi < 2; mi++)
#pragma unroll
                for (int p = 0; p < 4; p++) {
                    MMA_BF16(c[mi * 8 + p * 2 + 0], ah[mi], bl_[p][0], bl_[p][1]);
                    MMA_BF16(c[mi * 8 + p * 2 + 1], ah[mi], bl_[p][2], bl_[p][3]);
                }
        }
        __syncthreads();
    }

    // Epilogue
    const int row_in_frag = lane >> 2;
    const int col_in_frag = (lane & 3) * 2;
#pragma unroll
    for (int mi = 0; mi < 2; mi++) {
#pragma unroll
        for (int nj = 0; nj < 8; nj++) {
            const float* cc = c[mi * 8 + nj];
            const int col = n0 + wn * 64 + nj * 8 + col_in_frag;
            const float b0 = __ldg(bias + col), b1 = __ldg(bias + col + 1);
#pragma unroll
            for (int rr = 0; rr < 2; rr++) {
                const int m = m0 + wm * 32 + mi * 16 + row_in_frag + rr * 8;
                float ox = (cc[rr * 2 + 0] + b0) * scale;
                float oy = (cc[rr * 2 + 1] + b1) * scale;
                if (is_qkv) {
                    const int bb = m >> 10, n = m & 1023;
                    const int h = col >> 6, d = col & 63;
                    __nv_bfloat16 hx = __float2bfloat16(ox);
                    __nv_bfloat16 hy = __float2bfloat16(oy);
                    __nv_bfloat16 lx = __float2bfloat16(ox - __bfloat162float(hx));
                    __nv_bfloat16 ly = __float2bfloat16(oy - __bfloat162float(hy));
                    if (z == 2) {   // V: transposed store [B,H,D,N]
                        const size_t base = ((size_t)(bb * HH + h) * DD + d) * NN + n;
                        g_vth[base] = hx;       g_vtl[base] = lx;
                        g_vth[base + NN] = hy;  g_vtl[base + NN] = ly;
                    } else {
                        const size_t idx = (((size_t)(bb * HH + h) * NN + n) * DD + d);
                        __nv_bfloat16* dh = (z == 0) ? g_qh : g_kh;
                        __nv_bfloat16* dl = (z == 0) ? g_ql : g_kl;
                        *(__nv_bfloat162*)(dh + idx) = __nv_bfloat162(hx, hy);
                        *(__nv_bfloat162*)(dl + idx) = __nv_bfloat162(lx, ly);
                    }
                } else {
                    float2 o; o.x = ox; o.y = oy;
                    *(float2*)(out_param + (size_t)m * HIDD + col) = o;
                }
            }
        }
    }
}

// ---------------------------------------------------------------------------
// Tensor-core flash attention, double-buffered K/V.
// CTA: 128 queries, 8 warps. 16 key tiles of 64. smem: Q hi/lo (36KB) +
// 2 x K/V hi/lo buffers (36KB each) = 108KB. grid (8, 16, 8), 256 threads.
// ---------------------------------------------------------------------------
#define AQL_OFF 18432
#define KV_BUF0 36864
#define KV_STRIDE 36864
#define KL_OFF 9216
#define VH_OFF 18432
#define VL_OFF 27648
#define ATTN_SMEM (36864 + 2 * 36864)

__global__ __launch_bounds__(256, 1) void attn_kernel(const float* __restrict__ bias)
{
    extern __shared__ char smem[];
    const unsigned sb = smem_u32(smem);

    const int tid = threadIdx.x;
    const int wid = tid >> 5, lane = tid & 31;
    const int q0 = blockIdx.x * 128;
    const int h  = blockIdx.y;
    const int b  = blockIdx.z;

    const size_t qbase  = ((size_t)(b * HH + h) * NN + q0) * DD;
    const size_t kbase  = ((size_t)(b * HH + h) * NN) * DD;
    const size_t vtbase = ((size_t)(b * HH + h) * DD) * NN;

    auto load_kv = [&](int kt, unsigned dstb) {
#pragma unroll
        for (int t = 0; t < 2; t++) {
            const int ch = tid + t * 256;
            const int row = ch >> 3, c16 = ch & 7;
            CP_ASYNC16(dstb + row * 144 + c16 * 16,
                       g_kh + kbase + (size_t)(kt * 64 + row) * 64 + c16 * 8);
            CP_ASYNC16(dstb + KL_OFF + row * 144 + c16 * 16,
                       g_kl + kbase + (size_t)(kt * 64 + row) * 64 + c16 * 8);
            CP_ASYNC16(dstb + VH_OFF + row * 144 + c16 * 16,
                       g_vth + vtbase + (size_t)row * NN + kt * 64 + c16 * 8);
            CP_ASYNC16(dstb + VL_OFF + row * 144 + c16 * 16,
                       g_vtl + vtbase + (size_t)row * NN + kt * 64 + c16 * 8);
        }
    };

    // Load Q hi/lo + key tile 0 in one group
#pragma unroll
    for (int t = 0; t < 4; t++) {
        const int ch = tid + t * 256;
        const int row = ch >> 3, c16 = ch & 7;
        CP_ASYNC16(sb + row * 144 + c16 * 16, g_qh + qbase + row * 64 + c16 * 8);
        CP_ASYNC16(sb + AQL_OFF + row * 144 + c16 * 16, g_ql + qbase + row * 64 + c16 * 8);
    }
    load_kv(0, sb + KV_BUF0);
    CP_COMMIT();
    CP_WAIT(0);
    __syncthreads();

    float O[8][4];
#pragma unroll
    for (int i = 0; i < 8; i++)
#pragma unroll
        for (int j = 0; j < 4; j++) O[i][j] = 0.0f;
    float m1 = -1e30f, m2 = -1e30f, l1 = 0.0f, l2 = 0.0f;

    const unsigned qh_a = sb + (wid * 16 + (lane & 15)) * 144 + (lane >> 4) * 16;
    const unsigned ql_a = qh_a + AQL_OFF;
    const int nrow = ((lane >> 4) & 1) * 8 + (lane & 7);
    const int nc16 = (lane >> 3) & 1;
    const unsigned kv_lane = nrow * 144 + nc16 * 16;

    const int r1 = lane >> 2;
    const int cq = (lane & 3) * 2;
    const float* bgq = bias + ((size_t)(b * HH + h) * NN + q0 + wid * 16) * NN;

    for (int kt = 0; kt < 16; kt++) {
        const unsigned cb = sb + KV_BUF0 + (kt & 1) * KV_STRIDE;
        if (kt + 1 < 16) {
            load_kv(kt + 1, sb + KV_BUF0 + ((kt + 1) & 1) * KV_STRIDE);
            CP_COMMIT();
        }
        const unsigned kh_a = cb + kv_lane;
        const unsigned kl_a = kh_a + KL_OFF;
        const unsigned vh_a = kh_a + VH_OFF;
        const unsigned vl_a = kh_a + VL_OFF;

        // ---- S = qh*kh^T + qh*kl^T + ql*kh^T ----
        float S[8][4];
#pragma unroll
        for (int i = 0; i < 8; i++)
#pragma unroll
            for (int j = 0; j < 4; j++) S[i][j] = 0.0f;

#pragma unroll
        for (int j = 0; j < 4; j++) {       // k16 over d
            unsigned aqh[4], aql[4];
            LDMATRIX_X4(aqh[0], aqh[1], aqh[2], aqh[3], qh_a + j * 32);
            LDMATRIX_X4(aql[0], aql[1], aql[2], aql[3], ql_a + j * 32);
#pragma unroll
            for (int g = 0; g < 4; g++) {   // n16 over keys
                unsigned bh[4], bl[4];
                LDMATRIX_X4(bh[0], bh[1], bh[2], bh[3], kh_a + g * (16 * 144) + j * 32);
                LDMATRIX_X4(bl[0], bl[1], bl[2], bl[3], kl_a + g * (16 * 144) + j * 32);
                MMA_BF16(S[2 * g + 0], aqh, bh[0], bh[1]);
                MMA_BF16(S[2 * g + 1], aqh, bh[2], bh[3]);
                MMA_BF16(S[2 * g + 0], aqh, bl[0], bl[1]);
                MMA_BF16(S[2 * g + 1], aqh, bl[2], bl[3]);
                MMA_BF16(S[2 * g + 0], aql, bh[0], bh[1]);
                MMA_BF16(S[2 * g + 1], aql, bh[2], bh[3]);
            }
        }

        // ---- bias add ----
        const float* bt = bgq + kt * 64;
#pragma unroll
        for (int j = 0; j < 8; j++) {
            float2 f0 = *(const float2*)(bt + (size_t)r1 * NN + 8 * j + cq);
            float2 f1 = *(const float2*)(bt + (size_t)(r1 + 8) * NN + 8 * j + cq);
            S[j][0] += f0.x; S[j][1] += f0.y;
            S[j][2] += f1.x; S[j][3] += f1.y;
        }

        // ---- online softmax ----
        float mx1 = -1e30f, mx2 = -1e30f;
#pragma unroll
        for (int j = 0; j < 8; j++) {
            mx1 = fmaxf(mx1, fmaxf(S[j][0], S[j][1]));
            mx2 = fmaxf(mx2, fmaxf(S[j][2], S[j][3]));
        }
        mx1 = fmaxf(mx1, __shfl_xor_sync(0xffffffffu, mx1, 1));
        mx1 = fmaxf(mx1, __shfl_xor_sync(0xffffffffu, mx1, 2));
        mx2 = fmaxf(mx2, __shfl_xor_sync(0xffffffffu, mx2, 1));
        mx2 = fmaxf(mx2, __shfl_xor_sync(0xffffffffu, mx2, 2));
        const float mn1 = fmaxf(m1, mx1);
        const float mn2 = fmaxf(m2, mx2);
        const float co1 = __expf(m1 - mn1);
        const float co2 = __expf(m2 - mn2);
        float rs1 = 0.0f, rs2 = 0.0f;
#pragma unroll
        for (int j = 0; j < 8; j++) {
            S[j][0] = __expf(S[j][0] - mn1);
            S[j][1] = __expf(S[j][1] - mn1);
            S[j][2] = __expf(S[j][2] - mn2);
            S[j][3] = __expf(S[j][3] - mn2);
            rs1 += S[j][0] + S[j][1];
            rs2 += S[j][2] + S[j][3];
        }
        rs1 += __shfl_xor_sync(0xffffffffu, rs1, 1);
        rs1 += __shfl_xor_sync(0xffffffffu, rs1, 2);
        rs2 += __shfl_xor_sync(0xffffffffu, rs2, 1);
        rs2 += __shfl_xor_sync(0xffffffffu, rs2, 2);
        l1 = l1 * co1 + rs1;  m1 = mn1;
        l2 = l2 * co2 + rs2;  m2 = mn2;
#pragma unroll
        for (int i = 0; i < 8; i++) {
            O[i][0] *= co1; O[i][1] *= co1;
            O[i][2] *= co2; O[i][3] *= co2;
        }

        // ---- O += Ph*Vh + Ph*Vl + Pl*Vh ----
#pragma unroll
        for (int j = 0; j < 4; j++) {       // k16 over keys
            unsigned aph[4], apl[4];
            split2(S[2 * j][0],     S[2 * j][1],     aph[0], apl[0]);
            split2(S[2 * j][2],     S[2 * j][3],     aph[1], apl[1]);
            split2(S[2 * j + 1][0], S[2 * j + 1][1], aph[2], apl[2]);
            split2(S[2 * j + 1][2], S[2 * j + 1][3], aph[3], apl[3]);
#pragma unroll
            for (int g = 0; g < 4; g++) {   // n16 over d
                unsigned bh[4], bl[4];
                LDMATRIX_X4(bh[0], bh[1], bh[2], bh[3], vh_a + g * (16 * 144) + j * 32);
                LDMATRIX_X4(bl[0], bl[1], bl[2], bl[3], vl_a + g * (16 * 144) + j * 32);
                MMA_BF16(O[2 * g + 0], aph, bh[0], bh[1]);
                MMA_BF16(O[2 * g + 1], aph, bh[2], bh[3]);
                MMA_BF16(O[2 * g + 0], aph, bl[0], bl[1]);
                MMA_BF16(O[2 * g + 1], aph, bl[2], bl[3]);
                MMA_BF16(O[2 * g + 0], apl, bh[0], bh[1]);
                MMA_BF16(O[2 * g + 1], apl, bh[2], bh[3]);
            }
        }

        if (kt + 1 < 16) {
            CP_WAIT(0);
            __syncthreads();
        }
    }

    // ---- finalize -> ctx hi/lo bf16 ----
    const float inv1 = 1.0f / l1, inv2 = 1.0f / l2;
    const int n1 = q0 + wid * 16 + r1;
    const int n2 = n1 + 8;
#pragma unroll
    for (int i = 0; i < 8; i++) {
        const int d = 8 * i + cq;
        float x = O[i][0] * inv1, y = O[i][1] * inv1;
        float z = O[i][2] * inv2, w = O[i][3] * inv2;

        __nv_bfloat16 hx = __float2bfloat16(x), hy = __float2bfloat16(y);
        __nv_bfloat16 hz = __float2bfloat16(z), hw = __float2bfloat16(w);
        const size_t i1 = ((size_t)b * NN + n1) * HIDD + h * 64 + d;
        const size_t i2 = ((size_t)b * NN + n2) * HIDD + h * 64 + d;
        *(__nv_bfloat162*)(g_cxh + i1) = __nv_bfloat162(hx, hy);
        *(__nv_bfloat162*)(g_cxh + i2) = __nv_bfloat162(hz, hw);
        *(__nv_bfloat162*)(g_cxl + i1) = __nv_bfloat162(
            __float2bfloat16(x - __bfloat162float(hx)),
            __float2bfloat16(y - __bfloat162float(hy)));
        *(__nv_bfloat162*)(g_cxl + i2) = __nv_bfloat162(
            __float2bfloat16(z - __bfloat162float(hz)),
            __float2bfloat16(w - __bfloat162float(hw)));
    }
}

// ---------------------------------------------------------------------------
// Launch
// ---------------------------------------------------------------------------
extern "C" void kernel_launch(void* const* d_in, const int* in_sizes, int n_in,
                              void* d_out, int out_size)
{
    (void)in_sizes; (void)n_in; (void)out_size;
    const float* xq   = (const float*)d_in[0];
    const float* xk   = (const float*)d_in[1];
    const float* xv   = (const float*)d_in[2];
    const float* abia = (const float*)d_in[3];
    const float* Wq   = (const float*)d_in[4];
    const float* bq   = (const float*)d_in[5];
    const float* Wk   = (const float*)d_in[6];
    const float* bk   = (const float*)d_in[7];
    const float* Wv   = (const float*)d_in[8];
    const float* bv   = (const float*)d_in[9];
    const float* Wo   = (const float*)d_in[10];
    const float* bo   = (const float*)d_in[11];
    float* out = (float*)d_out;

    static int attr_set = 0;
    if (!attr_set) {
        cudaFuncSetAttribute(gemm_kernel,
                             cudaFuncAttributeMaxDynamicSharedMemorySize, GEMM_SMEM);
        cudaFuncSetAttribute(attn_kernel,
                             cudaFuncAttributeMaxDynamicSharedMemorySize, ATTN_SMEM);
        attr_set = 1;
    }

    conv_x_kernel<<<dim3(M_TOT * HIDD / 4 / 256, 3), 256>>>(xq, xk, xv);
    conv_w_kernel<<<dim3(32, 32, 4), dim3(32, 8)>>>(Wq, Wk, Wv, Wo);
    gemm_kernel<<<dim3(8, 64, 3), 256, GEMM_SMEM>>>(bq, bk, bv, nullptr, 1);
    attn_kernel<<<dim3(8, 16, 8), 256, ATTN_SMEM>>>(abia);
    gemm_kernel<<<dim3(8, 64, 1), 256, GEMM_SMEM>>>(bo, nullptr, nullptr, out, 0);
}

// round 9
// speedup vs baseline: 1.0507x; 1.0507x over previous
#include <cuda_runtime.h>
#include <cuda_bf16.h>

#define BB 8
#define NN 1024
#define HIDD 1024
#define HH 16
#define DD 64
#define M_TOT (BB * NN)   // 8192

// ---------------------------------------------------------------------------
// Scratch (static __device__ arrays — allocation-free per harness rules)
// ---------------------------------------------------------------------------
__device__ __nv_bfloat16 g_axh[3ll * M_TOT * HIDD];   // x hi  (q,k,v inputs)
__device__ __nv_bfloat16 g_axl[3ll * M_TOT * HIDD];   // x lo
__device__ __nv_bfloat16 g_bwh[4ll * HIDD * HIDD];    // W^T hi (q,k,v,o) [N,K]
__device__ __nv_bfloat16 g_bwl[4ll * HIDD * HIDD];    // W^T lo
__device__ __nv_bfloat16 g_qh[(size_t)BB * HH * NN * DD];  // [B,H,N,D] pre-scaled
__device__ __nv_bfloat16 g_ql[(size_t)BB * HH * NN * DD];
__device__ __nv_bfloat16 g_kh[(size_t)BB * HH * NN * DD];
__device__ __nv_bfloat16 g_kl[(size_t)BB * HH * NN * DD];
__device__ __nv_bfloat16 g_vth[(size_t)BB * HH * DD * NN]; // [B,H,D,N] transposed
__device__ __nv_bfloat16 g_vtl[(size_t)BB * HH * DD * NN];
__device__ __nv_bfloat16 g_cxh[(size_t)M_TOT * HIDD]; // ctx hi [B*N, H*D]
__device__ __nv_bfloat16 g_cxl[(size_t)M_TOT * HIDD]; // ctx lo

// ---------------------------------------------------------------------------
// PTX helpers (plain sm_80-era PTX — compiles at compute_103)
// ---------------------------------------------------------------------------
__device__ __forceinline__ unsigned smem_u32(const void* p) {
    unsigned a;
    asm("{ .reg .u64 t; cvta.to.shared.u64 t, %1; cvt.u32.u64 %0, t; }"
        : "=r"(a) : "l"(p));
    return a;
}
#define CP_ASYNC16(dst, src) \
    asm volatile("cp.async.cg.shared.global [%0], [%1], 16;" \
                 :: "r"(dst), "l"(src) : "memory")
#define CP_COMMIT() asm volatile("cp.async.commit_group;" ::: "memory")
#define CP_WAIT(n)  asm volatile("cp.async.wait_group %0;" :: "n"(n) : "memory")

#define LDMATRIX_X4(r0, r1, r2, r3, addr) \
    asm volatile("ldmatrix.sync.aligned.m8n8.x4.shared.b16 {%0,%1,%2,%3}, [%4];" \
                 : "=r"(r0), "=r"(r1), "=r"(r2), "=r"(r3) : "r"(addr))

#define MMA_BF16(c, a, b0, b1) \
    asm volatile("mma.sync.aligned.m16n8k16.row.col.f32.bf16.bf16.f32 " \
                 "{%0,%1,%2,%3}, {%4,%5,%6,%7}, {%8,%9}, {%0,%1,%2,%3};" \
                 : "+f"((c)[0]), "+f"((c)[1]), "+f"((c)[2]), "+f"((c)[3]) \
                 : "r"((a)[0]), "r"((a)[1]), "r"((a)[2]), "r"((a)[3]), \
                   "r"(b0), "r"(b1))

#define SWZ(x) ((x) ^ (((x) >> 3) & 0x70))

__device__ __forceinline__ unsigned pack_bf16(float x, float y) {
    __nv_bfloat162 t;
    t.x = __float2bfloat16(x);
    t.y = __float2bfloat16(y);
    return *(unsigned*)&t;
}
__device__ __forceinline__ void split2(float x, float y, unsigned& h, unsigned& l) {
    __nv_bfloat16 hx = __float2bfloat16(x), hy = __float2bfloat16(y);
    __nv_bfloat162 hh; hh.x = hx; hh.y = hy;
    h = *(unsigned*)&hh;
    l = pack_bf16(x - __bfloat162float(hx), y - __bfloat162float(hy));
}

// ---------------------------------------------------------------------------
// conv_x: fp32 [8192,1024] -> bf16 hi/lo. grid (8192, 3), 256 thr.
// ---------------------------------------------------------------------------
__global__ __launch_bounds__(256) void conv_x_kernel(
    const float* __restrict__ xq, const float* __restrict__ xk,
    const float* __restrict__ xv)
{
    const int z = blockIdx.y;
    const float* X = (z == 0) ? xq : (z == 1) ? xk : xv;
    __nv_bfloat16* Ah = g_axh + (size_t)z * M_TOT * HIDD;
    __nv_bfloat16* Al = g_axl + (size_t)z * M_TOT * HIDD;

    const size_t i = (size_t)blockIdx.x * 256 + threadIdx.x;  // float4 idx
    float4 v = ((const float4*)X)[i];

    __nv_bfloat16 h0 = __float2bfloat16(v.x), h1 = __float2bfloat16(v.y);
    __nv_bfloat16 h2 = __float2bfloat16(v.z), h3 = __float2bfloat16(v.w);
    float l0 = v.x - __bfloat162float(h0), l1 = v.y - __bfloat162float(h1);
    float l2 = v.z - __bfloat162float(h2), l3 = v.w - __bfloat162float(h3);

    __nv_bfloat162* Ah2 = (__nv_bfloat162*)Ah;
    __nv_bfloat162* Al2 = (__nv_bfloat162*)Al;
    Ah2[2 * i + 0] = __nv_bfloat162(h0, h1);
    Ah2[2 * i + 1] = __nv_bfloat162(h2, h3);
    Al2[2 * i + 0] = __nv_bfloat162(__float2bfloat16(l0), __float2bfloat16(l1));
    Al2[2 * i + 1] = __nv_bfloat162(__float2bfloat16(l2), __float2bfloat16(l3));
}

// ---------------------------------------------------------------------------
// conv_w: W [K,N] fp32 -> W^T [N,K] bf16 hi/lo. grid (32,32,4), block (32,8).
// ---------------------------------------------------------------------------
__global__ void conv_w_kernel(
    const float* __restrict__ Wq, const float* __restrict__ Wk,
    const float* __restrict__ Wv, const float* __restrict__ Wo)
{
    __shared__ float t[32][33];
    const int z = blockIdx.z;
    const float* W = (z == 0) ? Wq : (z == 1) ? Wk : (z == 2) ? Wv : Wo;
    __nv_bfloat16* Bh = g_bwh + (size_t)z * HIDD * HIDD;
    __nv_bfloat16* Bl = g_bwl + (size_t)z * HIDD * HIDD;

    const int tx = threadIdx.x, ty = threadIdx.y;
    const int k0 = blockIdx.x * 32, n0 = blockIdx.y * 32;

#pragma unroll
    for (int i = 0; i < 4; i++)
        t[ty + 8 * i][tx] = W[(size_t)(k0 + ty + 8 * i) * HIDD + n0 + tx];
    __syncthreads();
#pragma unroll
    for (int i = 0; i < 4; i++) {
        const int n = n0 + ty + 8 * i;
        const int k = k0 + tx;
        const float v = t[tx][ty + 8 * i];
        __nv_bfloat16 h = __float2bfloat16(v);
        Bh[(size_t)n * HIDD + k] = h;
        Bl[(size_t)n * HIDD + k] = __float2bfloat16(v - __bfloat162float(h));
    }
}

// ---------------------------------------------------------------------------
// mma.sync bf16 split GEMM, fused-term edition (unchanged from R8; correct).
// CTA tile M=128 x N=128, BK=32 k-blocks with hi|lo packed rows, 32 stages.
// ---------------------------------------------------------------------------
#define GEMM_SMEM (2 * 32768)
#define GEMM_STAGES 32

__global__ __launch_bounds__(256, 2) void gemm_kernel(
    const float* __restrict__ bq, const float* __restrict__ bk,
    const float* __restrict__ bv, float* out_param, int is_qkv)
{
    extern __shared__ char smem[];
    const unsigned sb = smem_u32(smem);
    const unsigned uA0 = sb, uB0 = sb + 16384;
    const unsigned uA1 = sb + 32768, uB1 = sb + 49152;

    const int tid = threadIdx.x;
    const int wid = tid >> 5, lane = tid & 31;
    const int wm = wid >> 1, wn = wid & 1;          // warp 4x2
    const int m0 = blockIdx.y * 128;
    const int n0 = blockIdx.x * 128;
    const int z = blockIdx.z;

    const __nv_bfloat16 *Ah, *Al, *Bh, *Bl;
    const float* bias;
    float scale;
    if (is_qkv) {
        Ah = g_axh + (size_t)z * M_TOT * HIDD;
        Al = g_axl + (size_t)z * M_TOT * HIDD;
        Bh = g_bwh + (size_t)z * HIDD * HIDD;
        Bl = g_bwl + (size_t)z * HIDD * HIDD;
        bias = (z == 0) ? bq : (z == 1) ? bk : bv;
        scale = (z == 0) ? 0.125f : 1.0f;
    } else {
        Ah = g_cxh; Al = g_cxl;
        Bh = g_bwh + 3ll * HIDD * HIDD;
        Bl = g_bwl + 3ll * HIDD * HIDD;
        bias = bq;            // bo passed in slot 0
        scale = 1.0f;
    }

    float c[16][4];
#pragma unroll
    for (int i = 0; i < 16; i++)
#pragma unroll
        for (int j = 0; j < 4; j++) c[i][j] = 0.0f;

    auto load_stage = [&](int kb, unsigned ua, unsigned ub) {
        const int kk0 = kb * 32;
#pragma unroll
        for (int t = 0; t < 4; t++) {
            const int ch = tid + t * 256;      // 0..1023
            const int row = ch >> 3;
            const int half = (ch >> 2) & 1;    // 0=hi, 1=lo
            const int c4 = ch & 3;             // 16B chunk within 64B
            const unsigned off = SWZ(row * 128 + half * 64 + c4 * 16);
            const __nv_bfloat16* sa =
                (half ? Al : Ah) + (size_t)(m0 + row) * HIDD + kk0 + c4 * 8;
            CP_ASYNC16(ua + off, sa);
            const __nv_bfloat16* sbp =
                (half ? Bl : Bh) + (size_t)(n0 + row) * HIDD + kk0 + c4 * 8;
            CP_ASYNC16(ub + off, sbp);
        }
        CP_COMMIT();
    };

    load_stage(0, uA0, uB0);

    const int a_r = wm * 32 + (lane & 15);
    const int a_c16 = (lane >> 4);
    const int b_r = wn * 64 + ((lane >> 4) & 1) * 8 + (lane & 7);
    const int b_c16 = (lane >> 3) & 1;

    for (int s = 0; s < GEMM_STAGES; s++) {
        const unsigned ua = (s & 1) ? uA1 : uA0;
        const unsigned ub = (s & 1) ? uB1 : uB0;
        if (s + 1 < GEMM_STAGES) {
            load_stage(s + 1, (s & 1) ? uA0 : uA1, (s & 1) ? uB0 : uB1);
            CP_WAIT(1);
        } else {
            CP_WAIT(0);
        }
        __syncthreads();

#pragma unroll
        for (int ks = 0; ks < 2; ks++) {
            unsigned ah[2][4];
#pragma unroll
            for (int mi = 0; mi < 2; mi++)
                LDMATRIX_X4(ah[mi][0], ah[mi][1], ah[mi][2], ah[mi][3],
                            ua + SWZ((a_r + mi * 16) * 128 + ks * 32 + a_c16 * 16));
            unsigned bh[4][4];
#pragma unroll
            for (int p = 0; p < 4; p++)
                LDMATRIX_X4(bh[p][0], bh[p][1], bh[p][2], bh[p][3],
                            ub + SWZ((b_r + p * 16) * 128 + ks * 32 + b_c16 * 16));
            // Ah*Bh
#pragma unroll
            for (int mi = 0; mi < 2; mi++)
#pragma unroll
                for (int p = 0; p < 4; p++) {
                    MMA_BF16(c[mi * 8 + p * 2 + 0], ah[mi], bh[p][0], bh[p][1]);
                    MMA_BF16(c[mi * 8 + p * 2 + 1], ah[mi], bh[p][2], bh[p][3]);
                }
            // Al*Bh (reuse bh)
            unsigned al_[2][4];
#pragma unroll
            for (int mi = 0; mi < 2; mi++)
                LDMATRIX_X4(al_[mi][0], al_[mi][1], al_[mi][2], al_[mi][3],
                            ua + SWZ((a_r + mi * 16) * 128 + 64 + ks * 32 + a_c16 * 16));
#pragma unroll
            for (int mi = 0; mi < 2; mi++)
#pragma unroll
                for (int p = 0; p < 4; p++) {
                    MMA_BF16(c[mi * 8 + p * 2 + 0], al_[mi], bh[p][0], bh[p][1]);
                    MMA_BF16(c[mi * 8 + p * 2 + 1], al_[mi], bh[p][2], bh[p][3]);
                }
            // Ah*Bl (reuse ah)
            unsigned bl_[4][4];
#pragma unroll
            for (int p = 0; p < 4; p++)
                LDMATRIX_X4(bl_[p][0], bl_[p][1], bl_[p][2], bl_[p][3],
                            ub + SWZ((b_r + p * 16) * 128 + 64 + ks * 32 + b_c16 * 16));
#pragma unroll
            for (int mi = 0; mi < 2; mi++)
#pragma unroll
                for (int p = 0; p < 4; p++) {
                    MMA_BF16(c[mi * 8 + p * 2 + 0], ah[mi], bl_[p][0], bl_[p][1]);
                    MMA_BF16(c[mi * 8 + p * 2 + 1], ah[mi], bl_[p][2], bl_[p][3]);
                }
        }
        __syncthreads();
    }

    // Epilogue
    const int row_in_frag = lane >> 2;
    const int col_in_frag = (lane & 3) * 2;
#pragma unroll
    for (int mi = 0; mi < 2; mi++) {
#pragma unroll
        for (int nj = 0; nj < 8; nj++) {
            const float* cc = c[mi * 8 + nj];
            const int col = n0 + wn * 64 + nj * 8 + col_in_frag;
            const float b0 = __ldg(bias + col), b1 = __ldg(bias + col + 1);
#pragma unroll
            for (int rr = 0; rr < 2; rr++) {
                const int m = m0 + wm * 32 + mi * 16 + row_in_frag + rr * 8;
                float ox = (cc[rr * 2 + 0] + b0) * scale;
                float oy = (cc[rr * 2 + 1] + b1) * scale;
                if (is_qkv) {
                    const int bb = m >> 10, n = m & 1023;
                    const int h = col >> 6, d = col & 63;
                    __nv_bfloat16 hx = __float2bfloat16(ox);
                    __nv_bfloat16 hy = __float2bfloat16(oy);
                    __nv_bfloat16 lx = __float2bfloat16(ox - __bfloat162float(hx));
                    __nv_bfloat16 ly = __float2bfloat16(oy - __bfloat162float(hy));
                    if (z == 2) {   // V: transposed store [B,H,D,N]
                        const size_t base = ((size_t)(bb * HH + h) * DD + d) * NN + n;
                        g_vth[base] = hx;       g_vtl[base] = lx;
                        g_vth[base + NN] = hy;  g_vtl[base + NN] = ly;
                    } else {
                        const size_t idx = (((size_t)(bb * HH + h) * NN + n) * DD + d);
                        __nv_bfloat16* dh = (z == 0) ? g_qh : g_kh;
                        __nv_bfloat16* dl = (z == 0) ? g_ql : g_kl;
                        *(__nv_bfloat162*)(dh + idx) = __nv_bfloat162(hx, hy);
                        *(__nv_bfloat162*)(dl + idx) = __nv_bfloat162(lx, ly);
                    }
                } else {
                    float2 o; o.x = ox; o.y = oy;
                    *(float2*)(out_param + (size_t)m * HIDD + col) = o;
                }
            }
        }
    }
}

// ---------------------------------------------------------------------------
// Tensor-core flash attention: Q register-resident, double-buffered K/V.
// CTA: 128 queries, 8 warps. Q staged through buffer 0 once, then held in
// registers (32/thread). smem = 2 x 36KB KV buffers = 72KB -> 2 CTAs/SM.
// grid (8, 16, 8), 256 threads, __launch_bounds__(256,2).
// ---------------------------------------------------------------------------
#define KV_STRIDE 36864
#define KL_OFF 9216
#define VH_OFF 18432
#define VL_OFF 27648
#define ATTN_SMEM (2 * 36864)

__global__ __launch_bounds__(256, 2) void attn_kernel(const float* __restrict__ bias)
{
    extern __shared__ char smem[];
    const unsigned sb = smem_u32(smem);

    const int tid = threadIdx.x;
    const int wid = tid >> 5, lane = tid & 31;
    const int q0 = blockIdx.x * 128;
    const int h  = blockIdx.y;
    const int b  = blockIdx.z;

    const size_t qbase  = ((size_t)(b * HH + h) * NN + q0) * DD;
    const size_t kbase  = ((size_t)(b * HH + h) * NN) * DD;
    const size_t vtbase = ((size_t)(b * HH + h) * DD) * NN;

    auto load_kv = [&](int kt, unsigned dstb) {
#pragma unroll
        for (int t = 0; t < 2; t++) {
            const int ch = tid + t * 256;
            const int row = ch >> 3, c16 = ch & 7;
            CP_ASYNC16(dstb + row * 144 + c16 * 16,
                       g_kh + kbase + (size_t)(kt * 64 + row) * 64 + c16 * 8);
            CP_ASYNC16(dstb + KL_OFF + row * 144 + c16 * 16,
                       g_kl + kbase + (size_t)(kt * 64 + row) * 64 + c16 * 8);
            CP_ASYNC16(dstb + VH_OFF + row * 144 + c16 * 16,
                       g_vth + vtbase + (size_t)row * NN + kt * 64 + c16 * 8);
            CP_ASYNC16(dstb + VL_OFF + row * 144 + c16 * 16,
                       g_vtl + vtbase + (size_t)row * NN + kt * 64 + c16 * 8);
        }
        CP_COMMIT();
    };

    // ---- Stage Q through buffer 0, then lift to registers ----
#pragma unroll
    for (int t = 0; t < 4; t++) {
        const int ch = tid + t * 256;
        const int row = ch >> 3, c16 = ch & 7;
        CP_ASYNC16(sb + row * 144 + c16 * 16, g_qh + qbase + row * 64 + c16 * 8);
        CP_ASYNC16(sb + 18432 + row * 144 + c16 * 16, g_ql + qbase + row * 64 + c16 * 8);
    }
    CP_COMMIT();
    CP_WAIT(0);
    __syncthreads();

    unsigned qh[4][4], ql[4][4];
    {
        const unsigned qa = sb + (wid * 16 + (lane & 15)) * 144 + (lane >> 4) * 16;
#pragma unroll
        for (int j = 0; j < 4; j++) {
            LDMATRIX_X4(qh[j][0], qh[j][1], qh[j][2], qh[j][3], qa + j * 32);
            LDMATRIX_X4(ql[j][0], ql[j][1], ql[j][2], ql[j][3], qa + 18432 + j * 32);
        }
    }
    __syncthreads();   // Q fully consumed; buffer 0 reusable

    load_kv(0, sb);

    float O[8][4];
#pragma unroll
    for (int i = 0; i < 8; i++)
#pragma unroll
        for (int j = 0; j < 4; j++) O[i][j] = 0.0f;
    float m1 = -1e30f, m2 = -1e30f, l1 = 0.0f, l2 = 0.0f;

    const int nrow = ((lane >> 4) & 1) * 8 + (lane & 7);
    const int nc16 = (lane >> 3) & 1;
    const unsigned kv_lane = nrow * 144 + nc16 * 16;

    const int r1 = lane >> 2;
    const int cq = (lane & 3) * 2;
    const float* bgq = bias + ((size_t)(b * HH + h) * NN + q0 + wid * 16) * NN;

    for (int kt = 0; kt < 16; kt++) {
        if (kt + 1 < 16) {
            load_kv(kt + 1, sb + ((kt + 1) & 1) * KV_STRIDE);
            CP_WAIT(1);
        } else {
            CP_WAIT(0);
        }
        __syncthreads();

        const unsigned cb = sb + (kt & 1) * KV_STRIDE;
        const unsigned kh_a = cb + kv_lane;
        const unsigned kl_a = kh_a + KL_OFF;
        const unsigned vh_a = kh_a + VH_OFF;
        const unsigned vl_a = kh_a + VL_OFF;

        // ---- S = qh*kh^T + qh*kl^T + ql*kh^T ----
        float S[8][4];
#pragma unroll
        for (int i = 0; i < 8; i++)
#pragma unroll
            for (int j = 0; j < 4; j++) S[i][j] = 0.0f;

#pragma unroll
        for (int j = 0; j < 4; j++) {       // k16 over d
#pragma unroll
            for (int g = 0; g < 4; g++) {   // n16 over keys
                unsigned bh[4], bl[4];
                LDMATRIX_X4(bh[0], bh[1], bh[2], bh[3], kh_a + g * (16 * 144) + j * 32);
                LDMATRIX_X4(bl[0], bl[1], bl[2], bl[3], kl_a + g * (16 * 144) + j * 32);
                MMA_BF16(S[2 * g + 0], qh[j], bh[0], bh[1]);
                MMA_BF16(S[2 * g + 1], qh[j], bh[2], bh[3]);
                MMA_BF16(S[2 * g + 0], qh[j], bl[0], bl[1]);
                MMA_BF16(S[2 * g + 1], qh[j], bl[2], bl[3]);
                MMA_BF16(S[2 * g + 0], ql[j], bh[0], bh[1]);
                MMA_BF16(S[2 * g + 1], ql[j], bh[2], bh[3]);
            }
        }

        // ---- bias add ----
        const float* bt = bgq + kt * 64;
#pragma unroll
        for (int j = 0; j < 8; j++) {
            float2 f0 = *(const float2*)(bt + (size_t)r1 * NN + 8 * j + cq);
            float2 f1 = *(const float2*)(bt + (size_t)(r1 + 8) * NN + 8 * j + cq);
            S[j][0] += f0.x; S[j][1] += f0.y;
            S[j][2] += f1.x; S[j][3] += f1.y;
        }

        // ---- online softmax ----
        float mx1 = -1e30f, mx2 = -1e30f;
#pragma unroll
        for (int j = 0; j < 8; j++) {
            mx1 = fmaxf(mx1, fmaxf(S[j][0], S[j][1]));
            mx2 = fmaxf(mx2, fmaxf(S[j][2], S[j][3]));
        }
        mx1 = fmaxf(mx1, __shfl_xor_sync(0xffffffffu, mx1, 1));
        mx1 = fmaxf(mx1, __shfl_xor_sync(0xffffffffu, mx1, 2));
        mx2 = fmaxf(mx2, __shfl_xor_sync(0xffffffffu, mx2, 1));
        mx2 = fmaxf(mx2, __shfl_xor_sync(0xffffffffu, mx2, 2));
        const float mn1 = fmaxf(m1, mx1);
        const float mn2 = fmaxf(m2, mx2);
        const float co1 = __expf(m1 - mn1);
        const float co2 = __expf(m2 - mn2);
        float rs1 = 0.0f, rs2 = 0.0f;
#pragma unroll
        for (int j = 0; j < 8; j++) {
            S[j][0] = __expf(S[j][0] - mn1);
            S[j][1] = __expf(S[j][1] - mn1);
            S[j][2] = __expf(S[j][2] - mn2);
            S[j][3] = __expf(S[j][3] - mn2);
            rs1 += S[j][0] + S[j][1];
            rs2 += S[j][2] + S[j][3];
        }
        rs1 += __shfl_xor_sync(0xffffffffu, rs1, 1);
        rs1 += __shfl_xor_sync(0xffffffffu, rs1, 2);
        rs2 += __shfl_xor_sync(0xffffffffu, rs2, 1);
        rs2 += __shfl_xor_sync(0xffffffffu, rs2, 2);
        l1 = l1 * co1 + rs1;  m1 = mn1;
        l2 = l2 * co2 + rs2;  m2 = mn2;
#pragma unroll
        for (int i = 0; i < 8; i++) {
            O[i][0] *= co1; O[i][1] *= co1;
            O[i][2] *= co2; O[i][3] *= co2;
        }

        // ---- O += Ph*Vh + Ph*Vl + Pl*Vh ----
#pragma unroll
        for (int j = 0; j < 4; j++) {       // k16 over keys
            unsigned aph[4], apl[4];
            split2(S[2 * j][0],     S[2 * j][1],     aph[0], apl[0]);
            split2(S[2 * j][2],     S[2 * j][3],     aph[1], apl[1]);
            split2(S[2 * j + 1][0], S[2 * j + 1][1], aph[2], apl[2]);
            split2(S[2 * j + 1][2], S[2 * j + 1][3], aph[3], apl[3]);
#pragma unroll
            for (int g = 0; g < 4; g++) {   // n16 over d
                unsigned bh[4], bl[4];
                LDMATRIX_X4(bh[0], bh[1], bh[2], bh[3], vh_a + g * (16 * 144) + j * 32);
                LDMATRIX_X4(bl[0], bl[1], bl[2], bl[3], vl_a + g * (16 * 144) + j * 32);
                MMA_BF16(O[2 * g + 0], aph, bh[0], bh[1]);
                MMA_BF16(O[2 * g + 1], aph, bh[2], bh[3]);
                MMA_BF16(O[2 * g + 0], aph, bl[0], bl[1]);
                MMA_BF16(O[2 * g + 1], aph, bl[2], bl[3]);
                MMA_BF16(O[2 * g + 0], apl, bh[0], bh[1]);
                MMA_BF16(O[2 * g + 1], apl, bh[2], bh[3]);
            }
        }

        __syncthreads();   // all warps done with buf[kt&1] before it is reloaded
    }

    // ---- finalize -> ctx hi/lo bf16 ----
    const float inv1 = 1.0f / l1, inv2 = 1.0f / l2;
    const int n1 = q0 + wid * 16 + r1;
    const int n2 = n1 + 8;
#pragma unroll
    for (int i = 0; i < 8; i++) {
        const int d = 8 * i + cq;
        float x = O[i][0] * inv1, y = O[i][1] * inv1;
        float z = O[i][2] * inv2, w = O[i][3] * inv2;

        __nv_bfloat16 hx = __float2bfloat16(x), hy = __float2bfloat16(y);
        __nv_bfloat16 hz = __float2bfloat16(z), hw = __float2bfloat16(w);
        const size_t i1 = ((size_t)b * NN + n1) * HIDD + h * 64 + d;
        const size_t i2 = ((size_t)b * NN + n2) * HIDD + h * 64 + d;
        *(__nv_bfloat162*)(g_cxh + i1) = __nv_bfloat162(hx, hy);
        *(__nv_bfloat162*)(g_cxh + i2) = __nv_bfloat162(hz, hw);
        *(__nv_bfloat162*)(g_cxl + i1) = __nv_bfloat162(
            __float2bfloat16(x - __bfloat162float(hx)),
            __float2bfloat16(y - __bfloat162float(hy)));
        *(__nv_bfloat162*)(g_cxl + i2) = __nv_bfloat162(
            __float2bfloat16(z - __bfloat162float(hz)),
            __float2bfloat16(w - __bfloat162float(hw)));
    }
}

// ---------------------------------------------------------------------------
// Launch
// ---------------------------------------------------------------------------
extern "C" void kernel_launch(void* const* d_in, const int* in_sizes, int n_in,
                              void* d_out, int out_size)
{
    (void)in_sizes; (void)n_in; (void)out_size;
    const float* xq   = (const float*)d_in[0];
    const float* xk   = (const float*)d_in[1];
    const float* xv   = (const float*)d_in[2];
    const float* abia = (const float*)d_in[3];
    const float* Wq   = (const float*)d_in[4];
    const float* bq   = (const float*)d_in[5];
    const float* Wk   = (const float*)d_in[6];
    const float* bk   = (const float*)d_in[7];
    const float* Wv   = (const float*)d_in[8];
    const float* bv   = (const float*)d_in[9];
    const float* Wo   = (const float*)d_in[10];
    const float* bo   = (const float*)d_in[11];
    float* out = (float*)d_out;

    static int attr_set = 0;
    if (!attr_set) {
        cudaFuncSetAttribute(gemm_kernel,
                             cudaFuncAttributeMaxDynamicSharedMemorySize, GEMM_SMEM);
        cudaFuncSetAttribute(attn_kernel,
                             cudaFuncAttributeMaxDynamicSharedMemorySize, ATTN_SMEM);
        attr_set = 1;
    }

    conv_x_kernel<<<dim3(M_TOT * HIDD / 4 / 256, 3), 256>>>(xq, xk, xv);
    conv_w_kernel<<<dim3(32, 32, 4), dim3(32, 8)>>>(Wq, Wk, Wv, Wo);
    gemm_kernel<<<dim3(8, 64, 3), 256, GEMM_SMEM>>>(bq, bk, bv, nullptr, 1);
    attn_kernel<<<dim3(8, 16, 8), 256, ATTN_SMEM>>>(abia);
    gemm_kernel<<<dim3(8, 64, 1), 256, GEMM_SMEM>>>(bo, nullptr, nullptr, out, 0);
}

// round 10
// speedup vs baseline: 1.2442x; 1.1842x over previous
#include <cuda_runtime.h>
#include <cuda_bf16.h>
#include <cuda_fp16.h>

#define BB 8
#define NN 1024
#define HIDD 1024
#define HH 16
#define DD 64
#define M_TOT (BB * NN)   // 8192

// ---------------------------------------------------------------------------
// Scratch (static __device__ arrays — allocation-free per harness rules)
// ---------------------------------------------------------------------------
__device__ __nv_bfloat16 g_axh[3ll * M_TOT * HIDD];   // x hi  (q,k,v inputs)
__device__ __nv_bfloat16 g_axl[3ll * M_TOT * HIDD];   // x lo
__device__ __nv_bfloat16 g_bwh[4ll * HIDD * HIDD];    // W^T hi (q,k,v,o) [N,K]
__device__ __nv_bfloat16 g_bwl[4ll * HIDD * HIDD];    // W^T lo
__device__ __half g_q16[(size_t)BB * HH * NN * DD];   // [B,H,N,D] pre-scaled, fp16
__device__ __half g_k16[(size_t)BB * HH * NN * DD];
__device__ __half g_vt16[(size_t)BB * HH * DD * NN];  // [B,H,D,N] transposed
__device__ __nv_bfloat16 g_cxh[(size_t)M_TOT * HIDD]; // ctx hi [B*N, H*D]
__device__ __nv_bfloat16 g_cxl[(size_t)M_TOT * HIDD]; // ctx lo

// ---------------------------------------------------------------------------
// PTX helpers (plain sm_80-era PTX — compiles at compute_103)
// ---------------------------------------------------------------------------
__device__ __forceinline__ unsigned smem_u32(const void* p) {
    unsigned a;
    asm("{ .reg .u64 t; cvta.to.shared.u64 t, %1; cvt.u32.u64 %0, t; }"
        : "=r"(a) : "l"(p));
    return a;
}
#define CP_ASYNC16(dst, src) \
    asm volatile("cp.async.cg.shared.global [%0], [%1], 16;" \
                 :: "r"(dst), "l"(src) : "memory")
#define CP_COMMIT() asm volatile("cp.async.commit_group;" ::: "memory")
#define CP_WAIT(n)  asm volatile("cp.async.wait_group %0;" :: "n"(n) : "memory")

#define LDMATRIX_X4(r0, r1, r2, r3, addr) \
    asm volatile("ldmatrix.sync.aligned.m8n8.x4.shared.b16 {%0,%1,%2,%3}, [%4];" \
                 : "=r"(r0), "=r"(r1), "=r"(r2), "=r"(r3) : "r"(addr))

#define MMA_BF16(c, a, b0, b1) \
    asm volatile("mma.sync.aligned.m16n8k16.row.col.f32.bf16.bf16.f32 " \
                 "{%0,%1,%2,%3}, {%4,%5,%6,%7}, {%8,%9}, {%0,%1,%2,%3};" \
                 : "+f"((c)[0]), "+f"((c)[1]), "+f"((c)[2]), "+f"((c)[3]) \
                 : "r"((a)[0]), "r"((a)[1]), "r"((a)[2]), "r"((a)[3]), \
                   "r"(b0), "r"(b1))

#define MMA_FP16(c, a, b0, b1) \
    asm volatile("mma.sync.aligned.m16n8k16.row.col.f32.f16.f16.f32 " \
                 "{%0,%1,%2,%3}, {%4,%5,%6,%7}, {%8,%9}, {%0,%1,%2,%3};" \
                 : "+f"((c)[0]), "+f"((c)[1]), "+f"((c)[2]), "+f"((c)[3]) \
                 : "r"((a)[0]), "r"((a)[1]), "r"((a)[2]), "r"((a)[3]), \
                   "r"(b0), "r"(b1))

#define SWZ(x) ((x) ^ (((x) >> 3) & 0x70))

__device__ __forceinline__ unsigned pack_half2(float x, float y) {
    __half2 t = __floats2half2_rn(x, y);
    return *(unsigned*)&t;
}

// ---------------------------------------------------------------------------
// conv_x: fp32 [8192,1024] -> bf16 hi/lo. grid (8192, 3), 256 thr.
// ---------------------------------------------------------------------------
__global__ __launch_bounds__(256) void conv_x_kernel(
    const float* __restrict__ xq, const float* __restrict__ xk,
    const float* __restrict__ xv)
{
    const int z = blockIdx.y;
    const float* X = (z == 0) ? xq : (z == 1) ? xk : xv;
    __nv_bfloat16* Ah = g_axh + (size_t)z * M_TOT * HIDD;
    __nv_bfloat16* Al = g_axl + (size_t)z * M_TOT * HIDD;

    const size_t i = (size_t)blockIdx.x * 256 + threadIdx.x;  // float4 idx
    float4 v = ((const float4*)X)[i];

    __nv_bfloat16 h0 = __float2bfloat16(v.x), h1 = __float2bfloat16(v.y);
    __nv_bfloat16 h2 = __float2bfloat16(v.z), h3 = __float2bfloat16(v.w);
    float l0 = v.x - __bfloat162float(h0), l1 = v.y - __bfloat162float(h1);
    float l2 = v.z - __bfloat162float(h2), l3 = v.w - __bfloat162float(h3);

    __nv_bfloat162* Ah2 = (__nv_bfloat162*)Ah;
    __nv_bfloat162* Al2 = (__nv_bfloat162*)Al;
    Ah2[2 * i + 0] = __nv_bfloat162(h0, h1);
    Ah2[2 * i + 1] = __nv_bfloat162(h2, h3);
    Al2[2 * i + 0] = __nv_bfloat162(__float2bfloat16(l0), __float2bfloat16(l1));
    Al2[2 * i + 1] = __nv_bfloat162(__float2bfloat16(l2), __float2bfloat16(l3));
}

// ---------------------------------------------------------------------------
// conv_w: W [K,N] fp32 -> W^T [N,K] bf16 hi/lo. grid (32,32,4), block (32,8).
// ---------------------------------------------------------------------------
__global__ void conv_w_kernel(
    const float* __restrict__ Wq, const float* __restrict__ Wk,
    const float* __restrict__ Wv, const float* __restrict__ Wo)
{
    __shared__ float t[32][33];
    const int z = blockIdx.z;
    const float* W = (z == 0) ? Wq : (z == 1) ? Wk : (z == 2) ? Wv : Wo;
    __nv_bfloat16* Bh = g_bwh + (size_t)z * HIDD * HIDD;
    __nv_bfloat16* Bl = g_bwl + (size_t)z * HIDD * HIDD;

    const int tx = threadIdx.x, ty = threadIdx.y;
    const int k0 = blockIdx.x * 32, n0 = blockIdx.y * 32;

#pragma unroll
    for (int i = 0; i < 4; i++)
        t[ty + 8 * i][tx] = W[(size_t)(k0 + ty + 8 * i) * HIDD + n0 + tx];
    __syncthreads();
#pragma unroll
    for (int i = 0; i < 4; i++) {
        const int n = n0 + ty + 8 * i;
        const int k = k0 + tx;
        const float v = t[tx][ty + 8 * i];
        __nv_bfloat16 h = __float2bfloat16(v);
        Bh[(size_t)n * HIDD + k] = h;
        Bl[(size_t)n * HIDD + k] = __float2bfloat16(v - __bfloat162float(h));
    }
}

// ---------------------------------------------------------------------------
// mma.sync bf16 split GEMM (mainloop unchanged; QKV epilogue now emits fp16).
// CTA tile M=128 x N=128, BK=32 k-blocks with hi|lo packed rows, 32 stages.
// ---------------------------------------------------------------------------
#define GEMM_SMEM (2 * 32768)
#define GEMM_STAGES 32

__global__ __launch_bounds__(256, 2) void gemm_kernel(
    const float* __restrict__ bq, const float* __restrict__ bk,
    const float* __restrict__ bv, float* out_param, int is_qkv)
{
    extern __shared__ char smem[];
    const unsigned sb = smem_u32(smem);
    const unsigned uA0 = sb, uB0 = sb + 16384;
    const unsigned uA1 = sb + 32768, uB1 = sb + 49152;

    const int tid = threadIdx.x;
    const int wid = tid >> 5, lane = tid & 31;
    const int wm = wid >> 1, wn = wid & 1;          // warp 4x2
    const int m0 = blockIdx.y * 128;
    const int n0 = blockIdx.x * 128;
    const int z = blockIdx.z;

    const __nv_bfloat16 *Ah, *Al, *Bh, *Bl;
    const float* bias;
    float scale;
    if (is_qkv) {
        Ah = g_axh + (size_t)z * M_TOT * HIDD;
        Al = g_axl + (size_t)z * M_TOT * HIDD;
        Bh = g_bwh + (size_t)z * HIDD * HIDD;
        Bl = g_bwl + (size_t)z * HIDD * HIDD;
        bias = (z == 0) ? bq : (z == 1) ? bk : bv;
        scale = (z == 0) ? 0.125f : 1.0f;
    } else {
        Ah = g_cxh; Al = g_cxl;
        Bh = g_bwh + 3ll * HIDD * HIDD;
        Bl = g_bwl + 3ll * HIDD * HIDD;
        bias = bq;            // bo passed in slot 0
        scale = 1.0f;
    }

    float c[16][4];
#pragma unroll
    for (int i = 0; i < 16; i++)
#pragma unroll
        for (int j = 0; j < 4; j++) c[i][j] = 0.0f;

    auto load_stage = [&](int kb, unsigned ua, unsigned ub) {
        const int kk0 = kb * 32;
#pragma unroll
        for (int t = 0; t < 4; t++) {
            const int ch = tid + t * 256;      // 0..1023
            const int row = ch >> 3;
            const int half = (ch >> 2) & 1;    // 0=hi, 1=lo
            const int c4 = ch & 3;             // 16B chunk within 64B
            const unsigned off = SWZ(row * 128 + half * 64 + c4 * 16);
            const __nv_bfloat16* sa =
                (half ? Al : Ah) + (size_t)(m0 + row) * HIDD + kk0 + c4 * 8;
            CP_ASYNC16(ua + off, sa);
            const __nv_bfloat16* sbp =
                (half ? Bl : Bh) + (size_t)(n0 + row) * HIDD + kk0 + c4 * 8;
            CP_ASYNC16(ub + off, sbp);
        }
        CP_COMMIT();
    };

    load_stage(0, uA0, uB0);

    const int a_r = wm * 32 + (lane & 15);
    const int a_c16 = (lane >> 4);
    const int b_r = wn * 64 + ((lane >> 4) & 1) * 8 + (lane & 7);
    const int b_c16 = (lane >> 3) & 1;

    for (int s = 0; s < GEMM_STAGES; s++) {
        const unsigned ua = (s & 1) ? uA1 : uA0;
        const unsigned ub = (s & 1) ? uB1 : uB0;
        if (s + 1 < GEMM_STAGES) {
            load_stage(s + 1, (s & 1) ? uA0 : uA1, (s & 1) ? uB0 : uB1);
            CP_WAIT(1);
        } else {
            CP_WAIT(0);
        }
        __syncthreads();

#pragma unroll
        for (int ks = 0; ks < 2; ks++) {
            unsigned ah[2][4];
#pragma unroll
            for (int mi = 0; mi < 2; mi++)
                LDMATRIX_X4(ah[mi][0], ah[mi][1], ah[mi][2], ah[mi][3],
                            ua + SWZ((a_r + mi * 16) * 128 + ks * 32 + a_c16 * 16));
            unsigned bh[4][4];
#pragma unroll
            for (int p = 0; p < 4; p++)
                LDMATRIX_X4(bh[p][0], bh[p][1], bh[p][2], bh[p][3],
                            ub + SWZ((b_r + p * 16) * 128 + ks * 32 + b_c16 * 16));
            // Ah*Bh
#pragma unroll
            for (int mi = 0; mi < 2; mi++)
#pragma unroll
                for (int p = 0; p < 4; p++) {
                    MMA_BF16(c[mi * 8 + p * 2 + 0], ah[mi], bh[p][0], bh[p][1]);
                    MMA_BF16(c[mi * 8 + p * 2 + 1], ah[mi], bh[p][2], bh[p][3]);
                }
            // Al*Bh (reuse bh)
            unsigned al_[2][4];
#pragma unroll
            for (int mi = 0; mi < 2; mi++)
                LDMATRIX_X4(al_[mi][0], al_[mi][1], al_[mi][2], al_[mi][3],
                            ua + SWZ((a_r + mi * 16) * 128 + 64 + ks * 32 + a_c16 * 16));
#pragma unroll
            for (int mi = 0; mi < 2; mi++)
#pragma unroll
                for (int p = 0; p < 4; p++) {
                    MMA_BF16(c[mi * 8 + p * 2 + 0], al_[mi], bh[p][0], bh[p][1]);
                    MMA_BF16(c[mi * 8 + p * 2 + 1], al_[mi], bh[p][2], bh[p][3]);
                }
            // Ah*Bl (reuse ah)
            unsigned bl_[4][4];
#pragma unroll
            for (int p = 0; p < 4; p++)
                LDMATRIX_X4(bl_[p][0], bl_[p][1], bl_[p][2], bl_[p][3],
                            ub + SWZ((b_r + p * 16) * 128 + 64 + ks * 32 + b_c16 * 16));
#pragma unroll
            for (int mi = 0; mi < 2; mi++)
#pragma unroll
                for (int p = 0; p < 4; p++) {
                    MMA_BF16(c[mi * 8 + p * 2 + 0], ah[mi], bl_[p][0], bl_[p][1]);
                    MMA_BF16(c[mi * 8 + p * 2 + 1], ah[mi], bl_[p][2], bl_[p][3]);
                }
        }
        __syncthreads();
    }

    // Epilogue
    const int row_in_frag = lane >> 2;
    const int col_in_frag = (lane & 3) * 2;
#pragma unroll
    for (int mi = 0; mi < 2; mi++) {
#pragma unroll
        for (int nj = 0; nj < 8; nj++) {
            const float* cc = c[mi * 8 + nj];
            const int col = n0 + wn * 64 + nj * 8 + col_in_frag;
            const float b0 = __ldg(bias + col), b1 = __ldg(bias + col + 1);
#pragma unroll
            for (int rr = 0; rr < 2; rr++) {
                const int m = m0 + wm * 32 + mi * 16 + row_in_frag + rr * 8;
                float ox = (cc[rr * 2 + 0] + b0) * scale;
                float oy = (cc[rr * 2 + 1] + b1) * scale;
                if (is_qkv) {
                    const int bb = m >> 10, n = m & 1023;
                    const int h = col >> 6, d = col & 63;
                    if (z == 2) {   // V: transposed fp16 store [B,H,D,N]
                        const size_t base = ((size_t)(bb * HH + h) * DD + d) * NN + n;
                        g_vt16[base]      = __float2half(ox);
                        g_vt16[base + NN] = __float2half(oy);
                    } else {        // Q/K: fp16 [B,H,N,D]
                        const size_t idx = (((size_t)(bb * HH + h) * NN + n) * DD + d);
                        __half* dst16 = (z == 0) ? g_q16 : g_k16;
                        *(__half2*)(dst16 + idx) = __floats2half2_rn(ox, oy);
                    }
                } else {
                    float2 o; o.x = ox; o.y = oy;
                    *(float2*)(out_param + (size_t)m * HIDD + col) = o;
                }
            }
        }
    }
}

// ---------------------------------------------------------------------------
// Tensor-core flash attention: single-term fp16, Q register-resident,
// double-buffered K/V. CTA: 128 queries, 8 warps. smem = 2 x 18KB = 36KB.
// grid (8, 16, 8), 256 threads, __launch_bounds__(256,2).
// ---------------------------------------------------------------------------
#define KV_STRIDE 18432
#define V_OFF 9216
#define ATTN_SMEM (2 * 18432)

__global__ __launch_bounds__(256, 2) void attn_kernel(const float* __restrict__ bias)
{
    extern __shared__ char smem[];
    const unsigned sb = smem_u32(smem);

    const int tid = threadIdx.x;
    const int wid = tid >> 5, lane = tid & 31;
    const int q0 = blockIdx.x * 128;
    const int h  = blockIdx.y;
    const int b  = blockIdx.z;

    const size_t qbase  = ((size_t)(b * HH + h) * NN + q0) * DD;
    const size_t kbase  = ((size_t)(b * HH + h) * NN) * DD;
    const size_t vtbase = ((size_t)(b * HH + h) * DD) * NN;

    auto load_kv = [&](int kt, unsigned dstb) {
#pragma unroll
        for (int t = 0; t < 2; t++) {
            const int ch = tid + t * 256;      // 0..511
            const int row = ch >> 3, c16 = ch & 7;
            CP_ASYNC16(dstb + row * 144 + c16 * 16,
                       g_k16 + kbase + (size_t)(kt * 64 + row) * 64 + c16 * 8);
            CP_ASYNC16(dstb + V_OFF + row * 144 + c16 * 16,
                       g_vt16 + vtbase + (size_t)row * NN + kt * 64 + c16 * 8);
        }
        CP_COMMIT();
    };

    // ---- Stage Q through buffer 0, then lift to registers ----
#pragma unroll
    for (int t = 0; t < 4; t++) {
        const int ch = tid + t * 256;          // 0..1023
        const int row = ch >> 3, c16 = ch & 7; // 128 rows x 8 chunks
        CP_ASYNC16(sb + row * 144 + c16 * 16, g_q16 + qbase + row * 64 + c16 * 8);
    }
    CP_COMMIT();
    CP_WAIT(0);
    __syncthreads();

    unsigned qf[4][4];
    {
        const unsigned qa = sb + (wid * 16 + (lane & 15)) * 144 + (lane >> 4) * 16;
#pragma unroll
        for (int j = 0; j < 4; j++)
            LDMATRIX_X4(qf[j][0], qf[j][1], qf[j][2], qf[j][3], qa + j * 32);
    }
    __syncthreads();   // Q fully consumed; buffer 0 reusable

    load_kv(0, sb);

    float O[8][4];
#pragma unroll
    for (int i = 0; i < 8; i++)
#pragma unroll
        for (int j = 0; j < 4; j++) O[i][j] = 0.0f;
    float m1 = -1e30f, m2 = -1e30f, l1 = 0.0f, l2 = 0.0f;

    const int nrow = ((lane >> 4) & 1) * 8 + (lane & 7);
    const int nc16 = (lane >> 3) & 1;
    const unsigned kv_lane = nrow * 144 + nc16 * 16;

    const int r1 = lane >> 2;
    const int cq = (lane & 3) * 2;
    const float* bgq = bias + ((size_t)(b * HH + h) * NN + q0 + wid * 16) * NN;

    for (int kt = 0; kt < 16; kt++) {
        if (kt + 1 < 16) {
            load_kv(kt + 1, sb + ((kt + 1) & 1) * KV_STRIDE);
            CP_WAIT(1);
        } else {
            CP_WAIT(0);
        }
        __syncthreads();

        const unsigned cb = sb + (kt & 1) * KV_STRIDE;
        const unsigned k_a = cb + kv_lane;
        const unsigned v_a = k_a + V_OFF;

        // ---- S = q * k^T  (single fp16 term) ----
        float S[8][4];
#pragma unroll
        for (int i = 0; i < 8; i++)
#pragma unroll
            for (int j = 0; j < 4; j++) S[i][j] = 0.0f;

#pragma unroll
        for (int j = 0; j < 4; j++) {       // k16 over d
#pragma unroll
            for (int g = 0; g < 4; g++) {   // n16 over keys
                unsigned bk_[4];
                LDMATRIX_X4(bk_[0], bk_[1], bk_[2], bk_[3], k_a + g * (16 * 144) + j * 32);
                MMA_FP16(S[2 * g + 0], qf[j], bk_[0], bk_[1]);
                MMA_FP16(S[2 * g + 1], qf[j], bk_[2], bk_[3]);
            }
        }

        // ---- bias add ----
        const float* bt = bgq + kt * 64;
#pragma unroll
        for (int j = 0; j < 8; j++) {
            float2 f0 = *(const float2*)(bt + (size_t)r1 * NN + 8 * j + cq);
            float2 f1 = *(const float2*)(bt + (size_t)(r1 + 8) * NN + 8 * j + cq);
            S[j][0] += f0.x; S[j][1] += f0.y;
            S[j][2] += f1.x; S[j][3] += f1.y;
        }

        // ---- online softmax ----
        float mx1 = -1e30f, mx2 = -1e30f;
#pragma unroll
        for (int j = 0; j < 8; j++) {
            mx1 = fmaxf(mx1, fmaxf(S[j][0], S[j][1]));
            mx2 = fmaxf(mx2, fmaxf(S[j][2], S[j][3]));
        }
        mx1 = fmaxf(mx1, __shfl_xor_sync(0xffffffffu, mx1, 1));
        mx1 = fmaxf(mx1, __shfl_xor_sync(0xffffffffu, mx1, 2));
        mx2 = fmaxf(mx2, __shfl_xor_sync(0xffffffffu, mx2, 1));
        mx2 = fmaxf(mx2, __shfl_xor_sync(0xffffffffu, mx2, 2));
        const float mn1 = fmaxf(m1, mx1);
        const float mn2 = fmaxf(m2, mx2);
        const float co1 = __expf(m1 - mn1);
        const float co2 = __expf(m2 - mn2);
        float rs1 = 0.0f, rs2 = 0.0f;
#pragma unroll
        for (int j = 0; j < 8; j++) {
            S[j][0] = __expf(S[j][0] - mn1);
            S[j][1] = __expf(S[j][1] - mn1);
            S[j][2] = __expf(S[j][2] - mn2);
            S[j][3] = __expf(S[j][3] - mn2);
            rs1 += S[j][0] + S[j][1];
            rs2 += S[j][2] + S[j][3];
        }
        rs1 += __shfl_xor_sync(0xffffffffu, rs1, 1);
        rs1 += __shfl_xor_sync(0xffffffffu, rs1, 2);
        rs2 += __shfl_xor_sync(0xffffffffu, rs2, 1);
        rs2 += __shfl_xor_sync(0xffffffffu, rs2, 2);
        l1 = l1 * co1 + rs1;  m1 = mn1;
        l2 = l2 * co2 + rs2;  m2 = mn2;
#pragma unroll
        for (int i = 0; i < 8; i++) {
            O[i][0] *= co1; O[i][1] *= co1;
            O[i][2] *= co2; O[i][3] *= co2;
        }

        // ---- O += P * V  (single fp16 term) ----
#pragma unroll
        for (int j = 0; j < 4; j++) {       // k16 over keys
            unsigned ap[4];
            ap[0] = pack_half2(S[2 * j][0],     S[2 * j][1]);
            ap[1] = pack_half2(S[2 * j][2],     S[2 * j][3]);
            ap[2] = pack_half2(S[2 * j + 1][0], S[2 * j + 1][1]);
            ap[3] = pack_half2(S[2 * j + 1][2], S[2 * j + 1][3]);
#pragma unroll
            for (int g = 0; g < 4; g++) {   // n16 over d
                unsigned bv_[4];
                LDMATRIX_X4(bv_[0], bv_[1], bv_[2], bv_[3], v_a + g * (16 * 144) + j * 32);
                MMA_FP16(O[2 * g + 0], ap, bv_[0], bv_[1]);
                MMA_FP16(O[2 * g + 1], ap, bv_[2], bv_[3]);
            }
        }

        __syncthreads();   // all warps done with buf[kt&1] before it is reloaded
    }

    // ---- finalize -> ctx hi/lo bf16 ----
    const float inv1 = 1.0f / l1, inv2 = 1.0f / l2;
    const int n1 = q0 + wid * 16 + r1;
    const int n2 = n1 + 8;
#pragma unroll
    for (int i = 0; i < 8; i++) {
        const int d = 8 * i + cq;
        float x = O[i][0] * inv1, y = O[i][1] * inv1;
        float z = O[i][2] * inv2, w = O[i][3] * inv2;

        __nv_bfloat16 hx = __float2bfloat16(x), hy = __float2bfloat16(y);
        __nv_bfloat16 hz = __float2bfloat16(z), hw = __float2bfloat16(w);
        const size_t i1 = ((size_t)b * NN + n1) * HIDD + h * 64 + d;
        const size_t i2 = ((size_t)b * NN + n2) * HIDD + h * 64 + d;
        *(__nv_bfloat162*)(g_cxh + i1) = __nv_bfloat162(hx, hy);
        *(__nv_bfloat162*)(g_cxh + i2) = __nv_bfloat162(hz, hw);
        *(__nv_bfloat162*)(g_cxl + i1) = __nv_bfloat162(
            __float2bfloat16(x - __bfloat162float(hx)),
            __float2bfloat16(y - __bfloat162float(hy)));
        *(__nv_bfloat162*)(g_cxl + i2) = __nv_bfloat162(
            __float2bfloat16(z - __bfloat162float(hz)),
            __float2bfloat16(w - __bfloat162float(hw)));
    }
}

// ---------------------------------------------------------------------------
// Launch
// ---------------------------------------------------------------------------
extern "C" void kernel_launch(void* const* d_in, const int* in_sizes, int n_in,
                              void* d_out, int out_size)
{
    (void)in_sizes; (void)n_in; (void)out_size;
    const float* xq   = (const float*)d_in[0];
    const float* xk   = (const float*)d_in[1];
    const float* xv   = (const float*)d_in[2];
    const float* abia = (const float*)d_in[3];
    const float* Wq   = (const float*)d_in[4];
    const float* bq   = (const float*)d_in[5];
    const float* Wk   = (const float*)d_in[6];
    const float* bk   = (const float*)d_in[7];
    const float* Wv   = (const float*)d_in[8];
    const float* bv   = (const float*)d_in[9];
    const float* Wo   = (const float*)d_in[10];
    const float* bo   = (const float*)d_in[11];
    float* out = (float*)d_out;

    static int attr_set = 0;
    if (!attr_set) {
        cudaFuncSetAttribute(gemm_kernel,
                             cudaFuncAttributeMaxDynamicSharedMemorySize, GEMM_SMEM);
        cudaFuncSetAttribute(attn_kernel,
                             cudaFuncAttributeMaxDynamicSharedMemorySize, ATTN_SMEM);
        attr_set = 1;
    }

    conv_x_kernel<<<dim3(M_TOT * HIDD / 4 / 256, 3), 256>>>(xq, xk, xv);
    conv_w_kernel<<<dim3(32, 32, 4), dim3(32, 8)>>>(Wq, Wk, Wv, Wo);
    gemm_kernel<<<dim3(8, 64, 3), 256, GEMM_SMEM>>>(bq, bk, bv, nullptr, 1);
    attn_kernel<<<dim3(8, 16, 8), 256, ATTN_SMEM>>>(abia);
    gemm_kernel<<<dim3(8, 64, 1), 256, GEMM_SMEM>>>(bo, nullptr, nullptr, out, 0);
}

// round 11
// speedup vs baseline: 2.1915x; 1.7613x over previous
#include <cuda_runtime.h>
#include <cuda_bf16.h>
#include <cuda_fp16.h>

#define BB 8
#define NN 1024
#define HIDD 1024
#define HH 16
#define DD 64
#define M_TOT (BB * NN)   // 8192

// ---------------------------------------------------------------------------
// Scratch (static __device__ arrays — allocation-free per harness rules)
// ---------------------------------------------------------------------------
__device__ __half g_ax16[3ll * M_TOT * HIDD];         // x fp16 (q,k,v inputs)
__device__ __half g_bw16[4ll * HIDD * HIDD];          // W^T fp16 (q,k,v,o) [N,K]
__device__ __half g_q16[(size_t)BB * HH * NN * DD];   // [B,H,N,D] pre-scaled
__device__ __half g_k16[(size_t)BB * HH * NN * DD];
__device__ __half g_vt16[(size_t)BB * HH * DD * NN];  // [B,H,D,N] transposed
__device__ __half g_cx16[(size_t)M_TOT * HIDD];       // ctx fp16 [B*N, H*D]

// ---------------------------------------------------------------------------
// PTX helpers (plain sm_80-era PTX — compiles at compute_103)
// ---------------------------------------------------------------------------
__device__ __forceinline__ unsigned smem_u32(const void* p) {
    unsigned a;
    asm("{ .reg .u64 t; cvta.to.shared.u64 t, %1; cvt.u32.u64 %0, t; }"
        : "=r"(a) : "l"(p));
    return a;
}
#define CP_ASYNC16(dst, src) \
    asm volatile("cp.async.cg.shared.global [%0], [%1], 16;" \
                 :: "r"(dst), "l"(src) : "memory")
#define CP_COMMIT() asm volatile("cp.async.commit_group;" ::: "memory")
#define CP_WAIT(n)  asm volatile("cp.async.wait_group %0;" :: "n"(n) : "memory")

#define LDMATRIX_X4(r0, r1, r2, r3, addr) \
    asm volatile("ldmatrix.sync.aligned.m8n8.x4.shared.b16 {%0,%1,%2,%3}, [%4];" \
                 : "=r"(r0), "=r"(r1), "=r"(r2), "=r"(r3) : "r"(addr))

#define MMA_FP16(c, a, b0, b1) \
    asm volatile("mma.sync.aligned.m16n8k16.row.col.f32.f16.f16.f32 " \
                 "{%0,%1,%2,%3}, {%4,%5,%6,%7}, {%8,%9}, {%0,%1,%2,%3};" \
                 : "+f"((c)[0]), "+f"((c)[1]), "+f"((c)[2]), "+f"((c)[3]) \
                 : "r"((a)[0]), "r"((a)[1]), "r"((a)[2]), "r"((a)[3]), \
                   "r"(b0), "r"(b1))

#define SWZ(x) ((x) ^ (((x) >> 3) & 0x70))

__device__ __forceinline__ unsigned pack_half2(float x, float y) {
    __half2 t = __floats2half2_rn(x, y);
    return *(unsigned*)&t;
}

// ---------------------------------------------------------------------------
// conv_x: fp32 [8192,1024] -> fp16. grid (8192, 3), 256 thr.
// ---------------------------------------------------------------------------
__global__ __launch_bounds__(256) void conv_x_kernel(
    const float* __restrict__ xq, const float* __restrict__ xk,
    const float* __restrict__ xv)
{
    const int z = blockIdx.y;
    const float* X = (z == 0) ? xq : (z == 1) ? xk : xv;
    __half* A = g_ax16 + (size_t)z * M_TOT * HIDD;

    const size_t i = (size_t)blockIdx.x * 256 + threadIdx.x;  // float4 idx
    float4 v = ((const float4*)X)[i];
    __half2* A2 = (__half2*)A;
    A2[2 * i + 0] = __floats2half2_rn(v.x, v.y);
    A2[2 * i + 1] = __floats2half2_rn(v.z, v.w);
}

// ---------------------------------------------------------------------------
// conv_w: W [K,N] fp32 -> W^T [N,K] fp16. grid (32,32,4), block (32,8).
// ---------------------------------------------------------------------------
__global__ void conv_w_kernel(
    const float* __restrict__ Wq, const float* __restrict__ Wk,
    const float* __restrict__ Wv, const float* __restrict__ Wo)
{
    __shared__ float t[32][33];
    const int z = blockIdx.z;
    const float* W = (z == 0) ? Wq : (z == 1) ? Wk : (z == 2) ? Wv : Wo;
    __half* Bt = g_bw16 + (size_t)z * HIDD * HIDD;

    const int tx = threadIdx.x, ty = threadIdx.y;
    const int k0 = blockIdx.x * 32, n0 = blockIdx.y * 32;

#pragma unroll
    for (int i = 0; i < 4; i++)
        t[ty + 8 * i][tx] = W[(size_t)(k0 + ty + 8 * i) * HIDD + n0 + tx];
    __syncthreads();
#pragma unroll
    for (int i = 0; i < 4; i++) {
        const int n = n0 + ty + 8 * i;
        const int k = k0 + tx;
        Bt[(size_t)n * HIDD + k] = __float2half(t[tx][ty + 8 * i]);
    }
}

// ---------------------------------------------------------------------------
// mma.sync fp16 single-term GEMM. CTA tile M=128 x N=128, BK=64 (128B rows),
// 16 stages, double-buffered cp.async (64KB). 8 warps 4x2, 32x64 per warp.
// is_qkv=1: z selects x/W/bias/dst; q scaled; v transposed. Outputs fp16.
// is_qkv=0: ctx fp16 x Wo -> fp32 out row-major.
// ---------------------------------------------------------------------------
#define GEMM_SMEM (2 * 32768)
#define GEMM_STAGES 16

__global__ __launch_bounds__(256, 2) void gemm_kernel(
    const float* __restrict__ bq, const float* __restrict__ bk,
    const float* __restrict__ bv, float* out_param, int is_qkv)
{
    extern __shared__ char smem[];
    const unsigned sb = smem_u32(smem);
    const unsigned uA0 = sb, uB0 = sb + 16384;
    const unsigned uA1 = sb + 32768, uB1 = sb + 49152;

    const int tid = threadIdx.x;
    const int wid = tid >> 5, lane = tid & 31;
    const int wm = wid >> 1, wn = wid & 1;          // warp 4x2
    const int m0 = blockIdx.y * 128;
    const int n0 = blockIdx.x * 128;
    const int z = blockIdx.z;

    const __half *A16, *B16;
    const float* bias;
    float scale;
    if (is_qkv) {
        A16 = g_ax16 + (size_t)z * M_TOT * HIDD;
        B16 = g_bw16 + (size_t)z * HIDD * HIDD;
        bias = (z == 0) ? bq : (z == 1) ? bk : bv;
        scale = (z == 0) ? 0.125f : 1.0f;
    } else {
        A16 = g_cx16;
        B16 = g_bw16 + 3ll * HIDD * HIDD;
        bias = bq;            // bo passed in slot 0
        scale = 1.0f;
    }

    float c[16][4];
#pragma unroll
    for (int i = 0; i < 16; i++)
#pragma unroll
        for (int j = 0; j < 4; j++) c[i][j] = 0.0f;

    // one stage = BK=64 fp16 = 128B per row
    auto load_stage = [&](int kb, unsigned ua, unsigned ub) {
        const int kk0 = kb * 64;
#pragma unroll
        for (int t = 0; t < 4; t++) {
            const int ch = tid + t * 256;      // 0..1023
            const int row = ch >> 3, c16 = ch & 7;
            const unsigned off = SWZ(row * 128 + c16 * 16);
            CP_ASYNC16(ua + off, A16 + (size_t)(m0 + row) * HIDD + kk0 + c16 * 8);
            CP_ASYNC16(ub + off, B16 + (size_t)(n0 + row) * HIDD + kk0 + c16 * 8);
        }
        CP_COMMIT();
    };

    load_stage(0, uA0, uB0);

    const int a_r = wm * 32 + (lane & 15);
    const int a_c16 = (lane >> 4);
    const int b_r = wn * 64 + ((lane >> 4) & 1) * 8 + (lane & 7);
    const int b_c16 = (lane >> 3) & 1;

    for (int s = 0; s < GEMM_STAGES; s++) {
        const unsigned ua = (s & 1) ? uA1 : uA0;
        const unsigned ub = (s & 1) ? uB1 : uB0;
        if (s + 1 < GEMM_STAGES) {
            load_stage(s + 1, (s & 1) ? uA0 : uA1, (s & 1) ? uB0 : uB1);
            CP_WAIT(1);
        } else {
            CP_WAIT(0);
        }
        __syncthreads();

#pragma unroll
        for (int ks = 0; ks < 4; ks++) {
            unsigned a[2][4];
#pragma unroll
            for (int mi = 0; mi < 2; mi++)
                LDMATRIX_X4(a[mi][0], a[mi][1], a[mi][2], a[mi][3],
                            ua + SWZ((a_r + mi * 16) * 128 + ks * 32 + a_c16 * 16));
            unsigned b[4][4];
#pragma unroll
            for (int p = 0; p < 4; p++)
                LDMATRIX_X4(b[p][0], b[p][1], b[p][2], b[p][3],
                            ub + SWZ((b_r + p * 16) * 128 + ks * 32 + b_c16 * 16));
#pragma unroll
            for (int mi = 0; mi < 2; mi++)
#pragma unroll
                for (int p = 0; p < 4; p++) {
                    MMA_FP16(c[mi * 8 + p * 2 + 0], a[mi], b[p][0], b[p][1]);
                    MMA_FP16(c[mi * 8 + p * 2 + 1], a[mi], b[p][2], b[p][3]);
                }
        }
        __syncthreads();
    }

    // Epilogue
    const int row_in_frag = lane >> 2;
    const int col_in_frag = (lane & 3) * 2;
#pragma unroll
    for (int mi = 0; mi < 2; mi++) {
#pragma unroll
        for (int nj = 0; nj < 8; nj++) {
            const float* cc = c[mi * 8 + nj];
            const int col = n0 + wn * 64 + nj * 8 + col_in_frag;
            const float b0 = __ldg(bias + col), b1 = __ldg(bias + col + 1);
#pragma unroll
            for (int rr = 0; rr < 2; rr++) {
                const int m = m0 + wm * 32 + mi * 16 + row_in_frag + rr * 8;
                float ox = (cc[rr * 2 + 0] + b0) * scale;
                float oy = (cc[rr * 2 + 1] + b1) * scale;
                if (is_qkv) {
                    const int bb = m >> 10, n = m & 1023;
                    const int h = col >> 6, d = col & 63;
                    if (z == 2) {   // V: transposed fp16 store [B,H,D,N]
                        const size_t base = ((size_t)(bb * HH + h) * DD + d) * NN + n;
                        g_vt16[base]      = __float2half(ox);
                        g_vt16[base + NN] = __float2half(oy);
                    } else {        // Q/K: fp16 [B,H,N,D]
                        const size_t idx = (((size_t)(bb * HH + h) * NN + n) * DD + d);
                        __half* dst16 = (z == 0) ? g_q16 : g_k16;
                        *(__half2*)(dst16 + idx) = __floats2half2_rn(ox, oy);
                    }
                } else {
                    float2 o; o.x = ox; o.y = oy;
                    *(float2*)(out_param + (size_t)m * HIDD + col) = o;
                }
            }
        }
    }
}

// ---------------------------------------------------------------------------
// Tensor-core flash attention: single-term fp16, Q register-resident,
// double-buffered K/V. CTA: 128 queries, 8 warps. smem = 2 x 18KB = 36KB.
// grid (8, 16, 8), 256 threads, __launch_bounds__(256,2).
// ---------------------------------------------------------------------------
#define KV_STRIDE 18432
#define V_OFF 9216
#define ATTN_SMEM (2 * 18432)

__global__ __launch_bounds__(256, 2) void attn_kernel(const float* __restrict__ bias)
{
    extern __shared__ char smem[];
    const unsigned sb = smem_u32(smem);

    const int tid = threadIdx.x;
    const int wid = tid >> 5, lane = tid & 31;
    const int q0 = blockIdx.x * 128;
    const int h  = blockIdx.y;
    const int b  = blockIdx.z;

    const size_t qbase  = ((size_t)(b * HH + h) * NN + q0) * DD;
    const size_t kbase  = ((size_t)(b * HH + h) * NN) * DD;
    const size_t vtbase = ((size_t)(b * HH + h) * DD) * NN;

    auto load_kv = [&](int kt, unsigned dstb) {
#pragma unroll
        for (int t = 0; t < 2; t++) {
            const int ch = tid + t * 256;      // 0..511
            const int row = ch >> 3, c16 = ch & 7;
            CP_ASYNC16(dstb + row * 144 + c16 * 16,
                       g_k16 + kbase + (size_t)(kt * 64 + row) * 64 + c16 * 8);
            CP_ASYNC16(dstb + V_OFF + row * 144 + c16 * 16,
                       g_vt16 + vtbase + (size_t)row * NN + kt * 64 + c16 * 8);
        }
        CP_COMMIT();
    };

    // ---- Stage Q through buffer 0, then lift to registers ----
#pragma unroll
    for (int t = 0; t < 4; t++) {
        const int ch = tid + t * 256;          // 0..1023
        const int row = ch >> 3, c16 = ch & 7; // 128 rows x 8 chunks
        CP_ASYNC16(sb + row * 144 + c16 * 16, g_q16 + qbase + row * 64 + c16 * 8);
    }
    CP_COMMIT();
    CP_WAIT(0);
    __syncthreads();

    unsigned qf[4][4];
    {
        const unsigned qa = sb + (wid * 16 + (lane & 15)) * 144 + (lane >> 4) * 16;
#pragma unroll
        for (int j = 0; j < 4; j++)
            LDMATRIX_X4(qf[j][0], qf[j][1], qf[j][2], qf[j][3], qa + j * 32);
    }
    __syncthreads();   // Q fully consumed; buffer 0 reusable

    load_kv(0, sb);

    float O[8][4];
#pragma unroll
    for (int i = 0; i < 8; i++)
#pragma unroll
        for (int j = 0; j < 4; j++) O[i][j] = 0.0f;
    float m1 = -1e30f, m2 = -1e30f, l1 = 0.0f, l2 = 0.0f;

    const int nrow = ((lane >> 4) & 1) * 8 + (lane & 7);
    const int nc16 = (lane >> 3) & 1;
    const unsigned kv_lane = nrow * 144 + nc16 * 16;

    const int r1 = lane >> 2;
    const int cq = (lane & 3) * 2;
    const float* bgq = bias + ((size_t)(b * HH + h) * NN + q0 + wid * 16) * NN;

    for (int kt = 0; kt < 16; kt++) {
        if (kt + 1 < 16) {
            load_kv(kt + 1, sb + ((kt + 1) & 1) * KV_STRIDE);
            CP_WAIT(1);
        } else {
            CP_WAIT(0);
        }
        __syncthreads();

        const unsigned cb = sb + (kt & 1) * KV_STRIDE;
        const unsigned k_a = cb + kv_lane;
        const unsigned v_a = k_a + V_OFF;

        // ---- S = q * k^T ----
        float S[8][4];
#pragma unroll
        for (int i = 0; i < 8; i++)
#pragma unroll
            for (int j = 0; j < 4; j++) S[i][j] = 0.0f;

#pragma unroll
        for (int j = 0; j < 4; j++) {       // k16 over d
#pragma unroll
            for (int g = 0; g < 4; g++) {   // n16 over keys
                unsigned bk_[4];
                LDMATRIX_X4(bk_[0], bk_[1], bk_[2], bk_[3], k_a + g * (16 * 144) + j * 32);
                MMA_FP16(S[2 * g + 0], qf[j], bk_[0], bk_[1]);
                MMA_FP16(S[2 * g + 1], qf[j], bk_[2], bk_[3]);
            }
        }

        // ---- bias add ----
        const float* bt = bgq + kt * 64;
#pragma unroll
        for (int j = 0; j < 8; j++) {
            float2 f0 = *(const float2*)(bt + (size_t)r1 * NN + 8 * j + cq);
            float2 f1 = *(const float2*)(bt + (size_t)(r1 + 8) * NN + 8 * j + cq);
            S[j][0] += f0.x; S[j][1] += f0.y;
            S[j][2] += f1.x; S[j][3] += f1.y;
        }

        // ---- online softmax ----
        float mx1 = -1e30f, mx2 = -1e30f;
#pragma unroll
        for (int j = 0; j < 8; j++) {
            mx1 = fmaxf(mx1, fmaxf(S[j][0], S[j][1]));
            mx2 = fmaxf(mx2, fmaxf(S[j][2], S[j][3]));
        }
        mx1 = fmaxf(mx1, __shfl_xor_sync(0xffffffffu, mx1, 1));
        mx1 = fmaxf(mx1, __shfl_xor_sync(0xffffffffu, mx1, 2));
        mx2 = fmaxf(mx2, __shfl_xor_sync(0xffffffffu, mx2, 1));
        mx2 = fmaxf(mx2, __shfl_xor_sync(0xffffffffu, mx2, 2));
        const float mn1 = fmaxf(m1, mx1);
        const float mn2 = fmaxf(m2, mx2);
        const float co1 = __expf(m1 - mn1);
        const float co2 = __expf(m2 - mn2);
        float rs1 = 0.0f, rs2 = 0.0f;
#pragma unroll
        for (int j = 0; j < 8; j++) {
            S[j][0] = __expf(S[j][0] - mn1);
            S[j][1] = __expf(S[j][1] - mn1);
            S[j][2] = __expf(S[j][2] - mn2);
            S[j][3] = __expf(S[j][3] - mn2);
            rs1 += S[j][0] + S[j][1];
            rs2 += S[j][2] + S[j][3];
        }
        rs1 += __shfl_xor_sync(0xffffffffu, rs1, 1);
        rs1 += __shfl_xor_sync(0xffffffffu, rs1, 2);
        rs2 += __shfl_xor_sync(0xffffffffu, rs2, 1);
        rs2 += __shfl_xor_sync(0xffffffffu, rs2, 2);
        l1 = l1 * co1 + rs1;  m1 = mn1;
        l2 = l2 * co2 + rs2;  m2 = mn2;
#pragma unroll
        for (int i = 0; i < 8; i++) {
            O[i][0] *= co1; O[i][1] *= co1;
            O[i][2] *= co2; O[i][3] *= co2;
        }

        // ---- O += P * V ----
#pragma unroll
        for (int j = 0; j < 4; j++) {       // k16 over keys
            unsigned ap[4];
            ap[0] = pack_half2(S[2 * j][0],     S[2 * j][1]);
            ap[1] = pack_half2(S[2 * j][2],     S[2 * j][3]);
            ap[2] = pack_half2(S[2 * j + 1][0], S[2 * j + 1][1]);
            ap[3] = pack_half2(S[2 * j + 1][2], S[2 * j + 1][3]);
#pragma unroll
            for (int g = 0; g < 4; g++) {   // n16 over d
                unsigned bv_[4];
                LDMATRIX_X4(bv_[0], bv_[1], bv_[2], bv_[3], v_a + g * (16 * 144) + j * 32);
                MMA_FP16(O[2 * g + 0], ap, bv_[0], bv_[1]);
                MMA_FP16(O[2 * g + 1], ap, bv_[2], bv_[3]);
            }
        }

        __syncthreads();   // all warps done with buf[kt&1] before it is reloaded
    }

    // ---- finalize -> ctx fp16 ----
    const float inv1 = 1.0f / l1, inv2 = 1.0f / l2;
    const int n1 = q0 + wid * 16 + r1;
    const int n2 = n1 + 8;
#pragma unroll
    for (int i = 0; i < 8; i++) {
        const int d = 8 * i + cq;
        const size_t i1 = ((size_t)b * NN + n1) * HIDD + h * 64 + d;
        const size_t i2 = ((size_t)b * NN + n2) * HIDD + h * 64 + d;
        *(__half2*)(g_cx16 + i1) = __floats2half2_rn(O[i][0] * inv1, O[i][1] * inv1);
        *(__half2*)(g_cx16 + i2) = __floats2half2_rn(O[i][2] * inv2, O[i][3] * inv2);
    }
}

// ---------------------------------------------------------------------------
// Launch
// ---------------------------------------------------------------------------
extern "C" void kernel_launch(void* const* d_in, const int* in_sizes, int n_in,
                              void* d_out, int out_size)
{
    (void)in_sizes; (void)n_in; (void)out_size;
    const float* xq   = (const float*)d_in[0];
    const float* xk   = (const float*)d_in[1];
    const float* xv   = (const float*)d_in[2];
    const float* abia = (const float*)d_in[3];
    const float* Wq   = (const float*)d_in[4];
    const float* bq   = (const float*)d_in[5];
    const float* Wk   = (const float*)d_in[6];
    const float* bk   = (const float*)d_in[7];
    const float* Wv   = (const float*)d_in[8];
    const float* bv   = (const float*)d_in[9];
    const float* Wo   = (const float*)d_in[10];
    const float* bo   = (const float*)d_in[11];
    float* out = (float*)d_out;

    static int attr_set = 0;
    if (!attr_set) {
        cudaFuncSetAttribute(gemm_kernel,
                             cudaFuncAttributeMaxDynamicSharedMemorySize, GEMM_SMEM);
        cudaFuncSetAttribute(attn_kernel,
                             cudaFuncAttributeMaxDynamicSharedMemorySize, ATTN_SMEM);
        attr_set = 1;
    }

    conv_x_kernel<<<dim3(M_TOT * HIDD / 4 / 256, 3), 256>>>(xq, xk, xv);
    conv_w_kernel<<<dim3(32, 32, 4), dim3(32, 8)>>>(Wq, Wk, Wv, Wo);
    gemm_kernel<<<dim3(8, 64, 3), 256, GEMM_SMEM>>>(bq, bk, bv, nullptr, 1);
    attn_kernel<<<dim3(8, 16, 8), 256, ATTN_SMEM>>>(abia);
    gemm_kernel<<<dim3(8, 64, 1), 256, GEMM_SMEM>>>(bo, nullptr, nullptr, out, 0);
}

// round 12
// speedup vs baseline: 2.3231x; 1.0601x over previous
#include <cuda_runtime.h>
#include <cuda_bf16.h>
#include <cuda_fp16.h>

#define BB 8
#define NN 1024
#define HIDD 1024
#define HH 16
#define DD 64
#define M_TOT (BB * NN)   // 8192

// ---------------------------------------------------------------------------
// Scratch (static __device__ arrays — allocation-free per harness rules)
// ---------------------------------------------------------------------------
__device__ __half g_ax16[3ll * M_TOT * HIDD];         // x fp16 (q,k,v inputs)
__device__ __half g_bw16[4ll * HIDD * HIDD];          // W^T fp16 (q,k,v,o) [N,K]
__device__ __half g_q16[(size_t)BB * HH * NN * DD];   // [B,H,N,D] pre-scaled
__device__ __half g_k16[(size_t)BB * HH * NN * DD];
__device__ __half g_vt16[(size_t)BB * HH * DD * NN];  // [B,H,D,N] transposed
__device__ __half g_cx16[(size_t)M_TOT * HIDD];       // ctx fp16 [B*N, H*D]

// ---------------------------------------------------------------------------
// PTX helpers (plain sm_80-era PTX — compiles at compute_103)
// ---------------------------------------------------------------------------
__device__ __forceinline__ unsigned smem_u32(const void* p) {
    unsigned a;
    asm("{ .reg .u64 t; cvta.to.shared.u64 t, %1; cvt.u32.u64 %0, t; }"
        : "=r"(a) : "l"(p));
    return a;
}
#define CP_ASYNC16(dst, src) \
    asm volatile("cp.async.cg.shared.global [%0], [%1], 16;" \
                 :: "r"(dst), "l"(src) : "memory")
#define CP_COMMIT() asm volatile("cp.async.commit_group;" ::: "memory")
#define CP_WAIT(n)  asm volatile("cp.async.wait_group %0;" :: "n"(n) : "memory")

#define LDMATRIX_X4(r0, r1, r2, r3, addr) \
    asm volatile("ldmatrix.sync.aligned.m8n8.x4.shared.b16 {%0,%1,%2,%3}, [%4];" \
                 : "=r"(r0), "=r"(r1), "=r"(r2), "=r"(r3) : "r"(addr))

#define MMA_FP16(c, a, b0, b1) \
    asm volatile("mma.sync.aligned.m16n8k16.row.col.f32.f16.f16.f32 " \
                 "{%0,%1,%2,%3}, {%4,%5,%6,%7}, {%8,%9}, {%0,%1,%2,%3};" \
                 : "+f"((c)[0]), "+f"((c)[1]), "+f"((c)[2]), "+f"((c)[3]) \
                 : "r"((a)[0]), "r"((a)[1]), "r"((a)[2]), "r"((a)[3]), \
                   "r"(b0), "r"(b1))

#define SWZ(x) ((x) ^ (((x) >> 3) & 0x70))

__device__ __forceinline__ unsigned pack_half2(float x, float y) {
    __half2 t = __floats2half2_rn(x, y);
    return *(unsigned*)&t;
}

// ---------------------------------------------------------------------------
// conv_x: fp32 [8192,1024] -> fp16. grid (8192, 3), 256 thr.
// ---------------------------------------------------------------------------
__global__ __launch_bounds__(256) void conv_x_kernel(
    const float* __restrict__ xq, const float* __restrict__ xk,
    const float* __restrict__ xv)
{
    const int z = blockIdx.y;
    const float* X = (z == 0) ? xq : (z == 1) ? xk : xv;
    __half* A = g_ax16 + (size_t)z * M_TOT * HIDD;

    const size_t i = (size_t)blockIdx.x * 256 + threadIdx.x;  // float4 idx
    float4 v = ((const float4*)X)[i];
    __half2* A2 = (__half2*)A;
    A2[2 * i + 0] = __floats2half2_rn(v.x, v.y);
    A2[2 * i + 1] = __floats2half2_rn(v.z, v.w);
}

// ---------------------------------------------------------------------------
// conv_w: W [K,N] fp32 -> W^T [N,K] fp16. grid (32,32,4), block (32,8).
// ---------------------------------------------------------------------------
__global__ void conv_w_kernel(
    const float* __restrict__ Wq, const float* __restrict__ Wk,
    const float* __restrict__ Wv, const float* __restrict__ Wo)
{
    __shared__ float t[32][33];
    const int z = blockIdx.z;
    const float* W = (z == 0) ? Wq : (z == 1) ? Wk : (z == 2) ? Wv : Wo;
    __half* Bt = g_bw16 + (size_t)z * HIDD * HIDD;

    const int tx = threadIdx.x, ty = threadIdx.y;
    const int k0 = blockIdx.x * 32, n0 = blockIdx.y * 32;

#pragma unroll
    for (int i = 0; i < 4; i++)
        t[ty + 8 * i][tx] = W[(size_t)(k0 + ty + 8 * i) * HIDD + n0 + tx];
    __syncthreads();
#pragma unroll
    for (int i = 0; i < 4; i++) {
        const int n = n0 + ty + 8 * i;
        const int k = k0 + tx;
        Bt[(size_t)n * HIDD + k] = __float2half(t[tx][ty + 8 * i]);
    }
}

// ---------------------------------------------------------------------------
// mma.sync fp16 single-term GEMM (unchanged from R11).
// CTA tile M=128 x N=128, BK=64, 16 stages, double-buffered cp.async.
// ---------------------------------------------------------------------------
#define GEMM_SMEM (2 * 32768)
#define GEMM_STAGES 16

__global__ __launch_bounds__(256, 2) void gemm_kernel(
    const float* __restrict__ bq, const float* __restrict__ bk,
    const float* __restrict__ bv, float* out_param, int is_qkv)
{
    extern __shared__ char smem[];
    const unsigned sb = smem_u32(smem);
    const unsigned uA0 = sb, uB0 = sb + 16384;
    const unsigned uA1 = sb + 32768, uB1 = sb + 49152;

    const int tid = threadIdx.x;
    const int wid = tid >> 5, lane = tid & 31;
    const int wm = wid >> 1, wn = wid & 1;          // warp 4x2
    const int m0 = blockIdx.y * 128;
    const int n0 = blockIdx.x * 128;
    const int z = blockIdx.z;

    const __half *A16, *B16;
    const float* bias;
    float scale;
    if (is_qkv) {
        A16 = g_ax16 + (size_t)z * M_TOT * HIDD;
        B16 = g_bw16 + (size_t)z * HIDD * HIDD;
        bias = (z == 0) ? bq : (z == 1) ? bk : bv;
        scale = (z == 0) ? 0.125f : 1.0f;
    } else {
        A16 = g_cx16;
        B16 = g_bw16 + 3ll * HIDD * HIDD;
        bias = bq;            // bo passed in slot 0
        scale = 1.0f;
    }

    float c[16][4];
#pragma unroll
    for (int i = 0; i < 16; i++)
#pragma unroll
        for (int j = 0; j < 4; j++) c[i][j] = 0.0f;

    auto load_stage = [&](int kb, unsigned ua, unsigned ub) {
        const int kk0 = kb * 64;
#pragma unroll
        for (int t = 0; t < 4; t++) {
            const int ch = tid + t * 256;      // 0..1023
            const int row = ch >> 3, c16 = ch & 7;
            const unsigned off = SWZ(row * 128 + c16 * 16);
            CP_ASYNC16(ua + off, A16 + (size_t)(m0 + row) * HIDD + kk0 + c16 * 8);
            CP_ASYNC16(ub + off, B16 + (size_t)(n0 + row) * HIDD + kk0 + c16 * 8);
        }
        CP_COMMIT();
    };

    load_stage(0, uA0, uB0);

    const int a_r = wm * 32 + (lane & 15);
    const int a_c16 = (lane >> 4);
    const int b_r = wn * 64 + ((lane >> 4) & 1) * 8 + (lane & 7);
    const int b_c16 = (lane >> 3) & 1;

    for (int s = 0; s < GEMM_STAGES; s++) {
        const unsigned ua = (s & 1) ? uA1 : uA0;
        const unsigned ub = (s & 1) ? uB1 : uB0;
        if (s + 1 < GEMM_STAGES) {
            load_stage(s + 1, (s & 1) ? uA0 : uA1, (s & 1) ? uB0 : uB1);
            CP_WAIT(1);
        } else {
            CP_WAIT(0);
        }
        __syncthreads();

#pragma unroll
        for (int ks = 0; ks < 4; ks++) {
            unsigned a[2][4];
#pragma unroll
            for (int mi = 0; mi < 2; mi++)
                LDMATRIX_X4(a[mi][0], a[mi][1], a[mi][2], a[mi][3],
                            ua + SWZ((a_r + mi * 16) * 128 + ks * 32 + a_c16 * 16));
            unsigned b[4][4];
#pragma unroll
            for (int p = 0; p < 4; p++)
                LDMATRIX_X4(b[p][0], b[p][1], b[p][2], b[p][3],
                            ub + SWZ((b_r + p * 16) * 128 + ks * 32 + b_c16 * 16));
#pragma unroll
            for (int mi = 0; mi < 2; mi++)
#pragma unroll
                for (int p = 0; p < 4; p++) {
                    MMA_FP16(c[mi * 8 + p * 2 + 0], a[mi], b[p][0], b[p][1]);
                    MMA_FP16(c[mi * 8 + p * 2 + 1], a[mi], b[p][2], b[p][3]);
                }
        }
        __syncthreads();
    }

    // Epilogue
    const int row_in_frag = lane >> 2;
    const int col_in_frag = (lane & 3) * 2;
#pragma unroll
    for (int mi = 0; mi < 2; mi++) {
#pragma unroll
        for (int nj = 0; nj < 8; nj++) {
            const float* cc = c[mi * 8 + nj];
            const int col = n0 + wn * 64 + nj * 8 + col_in_frag;
            const float b0 = __ldg(bias + col), b1 = __ldg(bias + col + 1);
#pragma unroll
            for (int rr = 0; rr < 2; rr++) {
                const int m = m0 + wm * 32 + mi * 16 + row_in_frag + rr * 8;
                float ox = (cc[rr * 2 + 0] + b0) * scale;
                float oy = (cc[rr * 2 + 1] + b1) * scale;
                if (is_qkv) {
                    const int bb = m >> 10, n = m & 1023;
                    const int h = col >> 6, d = col & 63;
                    if (z == 2) {   // V: transposed fp16 store [B,H,D,N]
                        const size_t base = ((size_t)(bb * HH + h) * DD + d) * NN + n;
                        g_vt16[base]      = __float2half(ox);
                        g_vt16[base + NN] = __float2half(oy);
                    } else {        // Q/K: fp16 [B,H,N,D]
                        const size_t idx = (((size_t)(bb * HH + h) * NN + n) * DD + d);
                        __half* dst16 = (z == 0) ? g_q16 : g_k16;
                        *(__half2*)(dst16 + idx) = __floats2half2_rn(ox, oy);
                    }
                } else {
                    float2 o; o.x = ox; o.y = oy;
                    *(float2*)(out_param + (size_t)m * HIDD + col) = o;
                }
            }
        }
    }
}

// ---------------------------------------------------------------------------
// Tensor-core flash attention: single-term fp16, Q register-resident,
// double-buffered K/V AND bias through cp.async.
// smem: 2 x 18KB KV + 2 x 34KB bias (128 rows x 272B, conflict-free stride)
// = 104KB -> 2 CTAs/SM. grid (8, 16, 8), 256 threads.
// ---------------------------------------------------------------------------
#define KV_STRIDE 18432
#define V_OFF 9216
#define BIAS0_OFF 36864
#define BIAS_STRIDE 34816          // 128 * 272
#define ATTN_SMEM (36864 + 2 * 34816)

__global__ __launch_bounds__(256, 2) void attn_kernel(const float* __restrict__ bias)
{
    extern __shared__ char smem[];
    const unsigned sb = smem_u32(smem);

    const int tid = threadIdx.x;
    const int wid = tid >> 5, lane = tid & 31;
    const int q0 = blockIdx.x * 128;
    const int h  = blockIdx.y;
    const int b  = blockIdx.z;

    const size_t qbase  = ((size_t)(b * HH + h) * NN + q0) * DD;
    const size_t kbase  = ((size_t)(b * HH + h) * NN) * DD;
    const size_t vtbase = ((size_t)(b * HH + h) * DD) * NN;
    const float* bg = bias + ((size_t)(b * HH + h) * NN + q0) * NN;

    auto load_kv = [&](int kt, unsigned dstb) {
#pragma unroll
        for (int t = 0; t < 2; t++) {
            const int ch = tid + t * 256;      // 0..511
            const int row = ch >> 3, c16 = ch & 7;
            CP_ASYNC16(dstb + row * 144 + c16 * 16,
                       g_k16 + kbase + (size_t)(kt * 64 + row) * 64 + c16 * 8);
            CP_ASYNC16(dstb + V_OFF + row * 144 + c16 * 16,
                       g_vt16 + vtbase + (size_t)row * NN + kt * 64 + c16 * 8);
        }
    };
    // bias tile: 128 q-rows x 64 k-cols fp32 -> smem rows of 272B
    auto load_bias = [&](int kt, unsigned dstb) {
#pragma unroll
        for (int t = 0; t < 8; t++) {
            const int ch = tid + t * 256;      // 0..2047
            const int row = ch >> 4, c16 = ch & 15;
            CP_ASYNC16(dstb + row * 272 + c16 * 16,
                       bg + (size_t)row * NN + kt * 64 + c16 * 4);
        }
    };

    // ---- Stage Q through KV buffer 0, then lift to registers ----
#pragma unroll
    for (int t = 0; t < 4; t++) {
        const int ch = tid + t * 256;          // 0..1023
        const int row = ch >> 3, c16 = ch & 7; // 128 rows x 8 chunks
        CP_ASYNC16(sb + row * 144 + c16 * 16, g_q16 + qbase + row * 64 + c16 * 8);
    }
    CP_COMMIT();
    CP_WAIT(0);
    __syncthreads();

    unsigned qf[4][4];
    {
        const unsigned qa = sb + (wid * 16 + (lane & 15)) * 144 + (lane >> 4) * 16;
#pragma unroll
        for (int j = 0; j < 4; j++)
            LDMATRIX_X4(qf[j][0], qf[j][1], qf[j][2], qf[j][3], qa + j * 32);
    }
    __syncthreads();   // Q fully consumed; buffer 0 reusable

    load_kv(0, sb);
    load_bias(0, sb + BIAS0_OFF);
    CP_COMMIT();

    float O[8][4];
#pragma unroll
    for (int i = 0; i < 8; i++)
#pragma unroll
        for (int j = 0; j < 4; j++) O[i][j] = 0.0f;
    float m1 = -1e30f, m2 = -1e30f, l1 = 0.0f, l2 = 0.0f;

    const int nrow = ((lane >> 4) & 1) * 8 + (lane & 7);
    const int nc16 = (lane >> 3) & 1;
    const unsigned kv_lane = nrow * 144 + nc16 * 16;

    const int r1 = lane >> 2;
    const int cq = (lane & 3) * 2;
    // per-thread smem bias addresses (row stride 272B; rows r1 and r1+8 of warp tile)
    const unsigned bias_lane = (wid * 16 + r1) * 272 + cq * 4;

    for (int kt = 0; kt < 16; kt++) {
        if (kt + 1 < 16) {
            load_kv(kt + 1, sb + ((kt + 1) & 1) * KV_STRIDE);
            load_bias(kt + 1, sb + BIAS0_OFF + ((kt + 1) & 1) * BIAS_STRIDE);
            CP_COMMIT();
            CP_WAIT(1);
        } else {
            CP_WAIT(0);
        }
        __syncthreads();

        const unsigned cb = sb + (kt & 1) * KV_STRIDE;
        const unsigned k_a = cb + kv_lane;
        const unsigned v_a = k_a + V_OFF;
        const unsigned bias_a = sb + BIAS0_OFF + (kt & 1) * BIAS_STRIDE + bias_lane;

        // ---- S = q * k^T ----
        float S[8][4];
#pragma unroll
        for (int i = 0; i < 8; i++)
#pragma unroll
            for (int j = 0; j < 4; j++) S[i][j] = 0.0f;

#pragma unroll
        for (int j = 0; j < 4; j++) {       // k16 over d
#pragma unroll
            for (int g = 0; g < 4; g++) {   // n16 over keys
                unsigned bk_[4];
                LDMATRIX_X4(bk_[0], bk_[1], bk_[2], bk_[3], k_a + g * (16 * 144) + j * 32);
                MMA_FP16(S[2 * g + 0], qf[j], bk_[0], bk_[1]);
                MMA_FP16(S[2 * g + 1], qf[j], bk_[2], bk_[3]);
            }
        }

        // ---- bias add (from smem, conflict-free stride) ----
#pragma unroll
        for (int j = 0; j < 8; j++) {
            float2 f0, f1;
            asm volatile("ld.shared.v2.f32 {%0, %1}, [%2];"
                         : "=f"(f0.x), "=f"(f0.y) : "r"(bias_a + j * 32));
            asm volatile("ld.shared.v2.f32 {%0, %1}, [%2];"
                         : "=f"(f1.x), "=f"(f1.y) : "r"(bias_a + 8 * 272 + j * 32));
            S[j][0] += f0.x; S[j][1] += f0.y;
            S[j][2] += f1.x; S[j][3] += f1.y;
        }

        // ---- online softmax ----
        float mx1 = -1e30f, mx2 = -1e30f;
#pragma unroll
        for (int j = 0; j < 8; j++) {
            mx1 = fmaxf(mx1, fmaxf(S[j][0], S[j][1]));
            mx2 = fmaxf(mx2, fmaxf(S[j][2], S[j][3]));
        }
        mx1 = fmaxf(mx1, __shfl_xor_sync(0xffffffffu, mx1, 1));
        mx1 = fmaxf(mx1, __shfl_xor_sync(0xffffffffu, mx1, 2));
        mx2 = fmaxf(mx2, __shfl_xor_sync(0xffffffffu, mx2, 1));
        mx2 = fmaxf(mx2, __shfl_xor_sync(0xffffffffu, mx2, 2));
        const float mn1 = fmaxf(m1, mx1);
        const float mn2 = fmaxf(m2, mx2);
        const float co1 = __expf(m1 - mn1);
        const float co2 = __expf(m2 - mn2);
        float rs1 = 0.0f, rs2 = 0.0f;
#pragma unroll
        for (int j = 0; j < 8; j++) {
            S[j][0] = __expf(S[j][0] - mn1);
            S[j][1] = __expf(S[j][1] - mn1);
            S[j][2] = __expf(S[j][2] - mn2);
            S[j][3] = __expf(S[j][3] - mn2);
            rs1 += S[j][0] + S[j][1];
            rs2 += S[j][2] + S[j][3];
        }
        rs1 += __shfl_xor_sync(0xffffffffu, rs1, 1);
        rs1 += __shfl_xor_sync(0xffffffffu, rs1, 2);
        rs2 += __shfl_xor_sync(0xffffffffu, rs2, 1);
        rs2 += __shfl_xor_sync(0xffffffffu, rs2, 2);
        l1 = l1 * co1 + rs1;  m1 = mn1;
        l2 = l2 * co2 + rs2;  m2 = mn2;
#pragma unroll
        for (int i = 0; i < 8; i++) {
            O[i][0] *= co1; O[i][1] *= co1;
            O[i][2] *= co2; O[i][3] *= co2;
        }

        // ---- O += P * V ----
#pragma unroll
        for (int j = 0; j < 4; j++) {       // k16 over keys
            unsigned ap[4];
            ap[0] = pack_half2(S[2 * j][0],     S[2 * j][1]);
            ap[1] = pack_half2(S[2 * j][2],     S[2 * j][3]);
            ap[2] = pack_half2(S[2 * j + 1][0], S[2 * j + 1][1]);
            ap[3] = pack_half2(S[2 * j + 1][2], S[2 * j + 1][3]);
#pragma unroll
            for (int g = 0; g < 4; g++) {   // n16 over d
                unsigned bv_[4];
                LDMATRIX_X4(bv_[0], bv_[1], bv_[2], bv_[3], v_a + g * (16 * 144) + j * 32);
                MMA_FP16(O[2 * g + 0], ap, bv_[0], bv_[1]);
                MMA_FP16(O[2 * g + 1], ap, bv_[2], bv_[3]);
            }
        }

        __syncthreads();   // all warps done with buf[kt&1] before it is reloaded
    }

    // ---- finalize -> ctx fp16 ----
    const float inv1 = 1.0f / l1, inv2 = 1.0f / l2;
    const int n1 = q0 + wid * 16 + r1;
    const int n2 = n1 + 8;
#pragma unroll
    for (int i = 0; i < 8; i++) {
        const int d = 8 * i + cq;
        const size_t i1 = ((size_t)b * NN + n1) * HIDD + h * 64 + d;
        const size_t i2 = ((size_t)b * NN + n2) * HIDD + h * 64 + d;
        *(__half2*)(g_cx16 + i1) = __floats2half2_rn(O[i][0] * inv1, O[i][1] * inv1);
        *(__half2*)(g_cx16 + i2) = __floats2half2_rn(O[i][2] * inv2, O[i][3] * inv2);
    }
}

// ---------------------------------------------------------------------------
// Launch
// ---------------------------------------------------------------------------
extern "C" void kernel_launch(void* const* d_in, const int* in_sizes, int n_in,
                              void* d_out, int out_size)
{
    (void)in_sizes; (void)n_in; (void)out_size;
    const float* xq   = (const float*)d_in[0];
    const float* xk   = (const float*)d_in[1];
    const float* xv   = (const float*)d_in[2];
    const float* abia = (const float*)d_in[3];
    const float* Wq   = (const float*)d_in[4];
    const float* bq   = (const float*)d_in[5];
    const float* Wk   = (const float*)d_in[6];
    const float* bk   = (const float*)d_in[7];
    const float* Wv   = (const float*)d_in[8];
    const float* bv   = (const float*)d_in[9];
    const float* Wo   = (const float*)d_in[10];
    const float* bo   = (const float*)d_in[11];
    float* out = (float*)d_out;

    static int attr_set = 0;
    if (!attr_set) {
        cudaFuncSetAttribute(gemm_kernel,
                             cudaFuncAttributeMaxDynamicSharedMemorySize, GEMM_SMEM);
        cudaFuncSetAttribute(attn_kernel,
                             cudaFuncAttributeMaxDynamicSharedMemorySize, ATTN_SMEM);
        attr_set = 1;
    }

    conv_x_kernel<<<dim3(M_TOT * HIDD / 4 / 256, 3), 256>>>(xq, xk, xv);
    conv_w_kernel<<<dim3(32, 32, 4), dim3(32, 8)>>>(Wq, Wk, Wv, Wo);
    gemm_kernel<<<dim3(8, 64, 3), 256, GEMM_SMEM>>>(bq, bk, bv, nullptr, 1);
    attn_kernel<<<dim3(8, 16, 8), 256, ATTN_SMEM>>>(abia);
    gemm_kernel<<<dim3(8, 64, 1), 256, GEMM_SMEM>>>(bo, nullptr, nullptr, out, 0);
}